// round 5
// baseline (speedup 1.0000x reference)
#include <cuda_runtime.h>

typedef unsigned long long u64;
#define FULL 0xFFFFFFFFu

__device__ __forceinline__ u64 pk2(float x, float y){
    u64 r; asm("mov.b64 %0,{%1,%2};" : "=l"(r) : "f"(x), "f"(y)); return r;
}
__device__ __forceinline__ float2 upk2(u64 a){
    float2 r; asm("mov.b64 {%0,%1},%2;" : "=f"(r.x), "=f"(r.y) : "l"(a)); return r;
}
__device__ __forceinline__ void fma2(u64 &d, u64 a, u64 b){
    asm("fma.rn.f32x2 %0,%1,%2,%0;" : "+l"(d) : "l"(a), "l"(b));
}
__device__ __forceinline__ float ex2(float x){
    float r; asm("ex2.approx.f32 %0,%1;" : "=f"(r) : "f"(x)); return r;
}
__device__ __forceinline__ float frcp(float x){
    float r; asm("rcp.approx.f32 %0,%1;" : "=f"(r) : "f"(x)); return r;
}

// per-CTA partials: [bh*4 + q4] slices
__device__ float g_Mp[512 * 4096];
__device__ float g_Sp[512 * 64];

// cT = log2(e) / softplus(delta)
__device__ __forceinline__ float get_cT(const float* __restrict__ delta){
    float d = delta[0];
    float t = (d > 20.f) ? d : log1pf(expf(d));
    return 1.44269504088896f / t;
}

#define BAR_PAIR(id) asm volatile("bar.sync %0, 64;" :: "r"(id) : "memory")

// =====================================================================
// Kernel 1: partial KV[d][e] and s[d] per (bh, quarter-of-L).
// grid 512, block 128 = 2 pairs of warps. Pair owns 512 rows as 16 tiles.
// Phase C uses LDS.128 v reads (half the LDS wavefronts of LDS.64).
// =====================================================================
__global__ __launch_bounds__(128, 4) void kv_kernel(
    const float* __restrict__ Kp, const float* __restrict__ Vp,
    const float* __restrict__ delta)
{
    __shared__ float pool[8832];   // k tiles [0,4352), v tiles [4352,8704), rs [8704,8768)

    const int bx   = blockIdx.x;
    const int bh   = bx >> 2;
    const int q4   = bx & 3;
    const int b    = bh >> 4, h = bh & 15;
    const int tid  = threadIdx.x;
    const int w    = tid >> 5, lane = tid & 31;
    const int pair = w >> 1, half = w & 1;
    const int eoff = half * 32;

    float* skt = pool + pair * 2176;
    float* svt = pool + 4352 + pair * 2176;
    float* sgp = pool + 8704 + pair * 32;

    const float cT = get_cT(delta);

    const long cbase = ((long)b * 4096L) * 1024L + h * 64L;
    const float* kb = Kp + cbase;
    const float* vb = Vp + cbase;

    u64 accA[16], accB[16];
    #pragma unroll
    for (int j = 0; j < 16; j++){ accA[j] = 0ull; accB[j] = 0ull; }
    float s0 = 0.f, s1 = 0.f;

    const int r_ld = lane >> 4;
    const int c_ld = (lane & 15) * 4;

    for (int t = 0; t < 16; t++){
        const long l0 = (long)q4 * 1024 + (long)pair * 512 + t * 32;

        // ---- Phase A: half0 loads k tile, half1 loads v tile ----
        {
            const float* src = half ? vb : kb;
            float* dst = half ? svt : skt;
            #pragma unroll
            for (int i = 0; i < 16; i++){
                const int r = 2 * i + r_ld;
                float4 v4 = *(const float4*)(src + (l0 + r) * 1024 + c_ld);
                *(float4*)(dst + r * 68 + c_ld) = v4;
            }
        }
        BAR_PAIR(1 + pair);

        // ---- Phase B: exp in place; rs per row (2 lanes/row, 1 shfl) ----
        {
            const int r  = half * 16 + (lane >> 1);
            float* rowp = skt + r * 68 + (lane & 1) * 32;
            float smA = 0.f, smB = 0.f;
            #pragma unroll
            for (int c = 0; c < 8; c++){
                float4 f = *(float4*)(rowp + 4 * c);
                f.x = ex2(cT * ((f.x < 0.f) ? -20.f : f.x));
                f.y = ex2(cT * ((f.y < 0.f) ? -20.f : f.y));
                f.z = ex2(cT * ((f.z < 0.f) ? -20.f : f.z));
                f.w = ex2(cT * ((f.w < 0.f) ? -20.f : f.w));
                *(float4*)(rowp + 4 * c) = f;
                smA += f.x + f.y; smB += f.z + f.w;
            }
            float sm = smA + smB;
            sm += __shfl_xor_sync(FULL, sm, 1);
            if ((lane & 1) == 0) sgp[r] = frcp(sm);
        }
        BAR_PAIR(1 + pair);

        // ---- Phase C: acc[d][e] += k''[d] * v[e], float4 v reads ----
        #pragma unroll 4
        for (int r = 0; r < 32; r++){
            float2 kp = *(const float2*)(skt + r * 68 + 2 * lane);
            float rs = sgp[r];
            float k0 = kp.x * rs, k1 = kp.y * rs;
            const u64 kk0 = pk2(k0, k0), kk1 = pk2(k1, k1);
            s0 += k0; s1 += k1;
            const float* vrow = svt + r * 68 + eoff;
            #pragma unroll
            for (int j2 = 0; j2 < 8; j2++){
                float4 v4 = *(const float4*)(vrow + 4 * j2);
                u64 v01 = pk2(v4.x, v4.y), v23 = pk2(v4.z, v4.w);
                fma2(accA[2*j2],   kk0, v01); fma2(accA[2*j2+1], kk0, v23);
                fma2(accB[2*j2],   kk1, v01); fma2(accB[2*j2+1], kk1, v23);
            }
        }
        BAR_PAIR(1 + pair);
    }

    // ---- combine pairs in smem, write per-CTA partial ----
    __syncthreads();
    float* sM  = pool;            // 64 x 66
    float* sSh = pool + 4224;
    const int d0 = 2 * lane, d1 = d0 + 1;
    if (pair == 0){
        #pragma unroll
        for (int j = 0; j < 16; j++){
            *(float2*)&sM[d0 * 66 + eoff + 2 * j] = upk2(accA[j]);
            *(float2*)&sM[d1 * 66 + eoff + 2 * j] = upk2(accB[j]);
        }
        if (half == 0){ sSh[d0] = s0; sSh[d1] = s1; }
    }
    __syncthreads();
    if (pair == 1){
        #pragma unroll
        for (int j = 0; j < 16; j++){
            float2 a = upk2(accA[j]);
            float2 c0 = *(float2*)&sM[d0 * 66 + eoff + 2 * j];
            c0.x += a.x; c0.y += a.y;
            *(float2*)&sM[d0 * 66 + eoff + 2 * j] = c0;
            float2 c = upk2(accB[j]);
            float2 c1 = *(float2*)&sM[d1 * 66 + eoff + 2 * j];
            c1.x += c.x; c1.y += c.y;
            *(float2*)&sM[d1 * 66 + eoff + 2 * j] = c1;
        }
        if (half == 0){ sSh[d0] += s0; sSh[d1] += s1; }
    }
    __syncthreads();
    float* Mout = g_Mp + (long)bx * 4096;
    for (int i = tid; i < 4096; i += 128)
        Mout[i] = sM[(i >> 6) * 66 + (i & 63)];
    if (tid < 64) g_Sp[bx * 64 + tid] = sSh[tid];
}

// =====================================================================
// Kernel 2: out[l] = g_l * (E_l @ M). grid (128 bh, 4), block 128 =
// 2 pairs. Pair shares a q tile; warp half owns output cols [32h,32h+32),
// lane owns ONE output col -> M slice is 32 u64 (64 regs) -> 5 CTAs/SM.
// Phase C: per 2 rows: 32 LDS.128 + 64 FMA2, epilogue direct STG.
// =====================================================================
__global__ __launch_bounds__(128, 5) void out_kernel(
    const float* __restrict__ Qp, float* __restrict__ Out,
    const float* __restrict__ delta)
{
    __shared__ float pool[4352];   // sM[64][68] during init, then 2 q tiles (2176 each)
    __shared__ float sS[64];
    __shared__ float sg[2][32];

    const int bh   = blockIdx.x;
    const int b    = bh >> 4, h = bh & 15;
    const int ck   = blockIdx.y;
    const int tid  = threadIdx.x;
    const int w    = tid >> 5, lane = tid & 31;
    const int pair = w >> 1, half = w & 1;

    const float cT = get_cT(delta);

    if (tid < 64){
        float s = 0.f;
        #pragma unroll
        for (int p = 0; p < 4; p++) s += g_Sp[(bh * 4 + p) * 64 + tid];
        sS[tid] = s;
    }
    // sum 4 M partials into pool as sM[d*68 + e]
    for (int i = tid; i < 1024; i += 128){
        const int d = i >> 4, c4 = (i & 15) * 4;
        float4 a = make_float4(0.f, 0.f, 0.f, 0.f);
        #pragma unroll
        for (int p = 0; p < 4; p++){
            float4 v = *(const float4*)(g_Mp + (long)(bh * 4 + p) * 4096 + d * 64 + c4);
            a.x += v.x; a.y += v.y; a.z += v.z; a.w += v.w;
        }
        *(float4*)(pool + d * 68 + c4) = a;
    }
    __syncthreads();

    // register M slice: lane owns output col e; MC[j] = (M[2j][e], M[2j+1][e])
    const int e = 32 * half + lane;
    u64 MC[32];
    #pragma unroll
    for (int j = 0; j < 32; j++)
        MC[j] = pk2(pool[(2 * j) * 68 + e], pool[(2 * j + 1) * 68 + e]);
    __syncthreads();   // done with sM; pool becomes q tiles

    float* sq = pool + pair * 2176;
    const long cbase = ((long)b * 4096L) * 1024L + h * 64L;
    const int r_ld = lane >> 4;
    const int c_ld = (lane & 15) * 4;

    for (int t = ck * 2 + pair; t < 128; t += 8){
        const long l0 = (long)t * 32;

        // ---- Phase A: warp loads its 16 rows of the shared 32-row tile ----
        #pragma unroll
        for (int i = 0; i < 8; i++){
            const int r = 16 * half + 2 * i + r_ld;
            float4 v4 = *(const float4*)(Qp + cbase + (l0 + r) * 1024 + c_ld);
            *(float4*)(sq + r * 68 + c_ld) = v4;
        }
        BAR_PAIR(1 + pair);

        // ---- Phase B: exp + row sums (2 lanes/row, 1 shfl each) ----
        {
            const int r  = 16 * half + (lane >> 1);
            float* rowp = sq + r * 68 + (lane & 1) * 32;
            const float* sp = sS + (lane & 1) * 32;
            float sm = 0.f, u = 0.f;
            #pragma unroll
            for (int c = 0; c < 8; c++){
                float4 f = *(float4*)(rowp + 4 * c);
                float4 s4 = *(const float4*)(sp + 4 * c);
                f.x = ex2(cT * ((f.x < 0.f) ? -20.f : f.x));
                f.y = ex2(cT * ((f.y < 0.f) ? -20.f : f.y));
                f.z = ex2(cT * ((f.z < 0.f) ? -20.f : f.z));
                f.w = ex2(cT * ((f.w < 0.f) ? -20.f : f.w));
                *(float4*)(rowp + 4 * c) = f;
                sm += (f.x + f.y) + (f.z + f.w);
                u = fmaf(f.x, s4.x, fmaf(f.y, s4.y, fmaf(f.z, s4.z, fmaf(f.w, s4.w, u))));
            }
            sm += __shfl_xor_sync(FULL, sm, 1);
            u  += __shfl_xor_sync(FULL, u,  1);
            if ((lane & 1) == 0) sg[pair][r] = frcp(u + 1e-6f * sm);
        }
        BAR_PAIR(1 + pair);

        // ---- Phase C: matvec, 2 rows interleaved, lane owns 1 output ----
        #pragma unroll 2
        for (int rr = 0; rr < 16; rr++){
            const float* q0 = sq + (2 * rr) * 68;
            const float* q1 = q0 + 68;
            u64 o0 = 0ull, o1 = 0ull;
            #pragma unroll
            for (int m = 0; m < 16; m++){
                float4 a = *(const float4*)(q0 + 4 * m);
                float4 c = *(const float4*)(q1 + 4 * m);
                fma2(o0, pk2(a.x, a.y), MC[2 * m]);
                fma2(o0, pk2(a.z, a.w), MC[2 * m + 1]);
                fma2(o1, pk2(c.x, c.y), MC[2 * m]);
                fma2(o1, pk2(c.z, c.w), MC[2 * m + 1]);
            }
            float2 A = upk2(o0), B = upk2(o1);
            Out[cbase + (l0 + 2 * rr)     * 1024 + e] = (A.x + A.y) * sg[pair][2 * rr];
            Out[cbase + (l0 + 2 * rr + 1) * 1024 + e] = (B.x + B.y) * sg[pair][2 * rr + 1];
        }
        BAR_PAIR(1 + pair);
    }
}

extern "C" void kernel_launch(void* const* d_in, const int* in_sizes, int n_in,
                              void* d_out, int out_size)
{
    const float* Q     = (const float*)d_in[0];
    const float* K     = (const float*)d_in[1];
    const float* V     = (const float*)d_in[2];
    const float* delta = (const float*)d_in[3];
    float* Out = (float*)d_out;

    kv_kernel<<<512, 128>>>(K, V, delta);
    out_kernel<<<dim3(128, 4), 128>>>(Q, Out, delta);
}

// round 6
// speedup vs baseline: 1.1863x; 1.1863x over previous
#include <cuda_runtime.h>

typedef unsigned long long u64;
#define FULL 0xFFFFFFFFu

__device__ __forceinline__ u64 pk2(float x, float y){
    u64 r; asm("mov.b64 %0,{%1,%2};" : "=l"(r) : "f"(x), "f"(y)); return r;
}
__device__ __forceinline__ float2 upk2(u64 a){
    float2 r; asm("mov.b64 {%0,%1},%2;" : "=f"(r.x), "=f"(r.y) : "l"(a)); return r;
}
__device__ __forceinline__ void fma2(u64 &d, u64 a, u64 b){
    asm("fma.rn.f32x2 %0,%1,%2,%0;" : "+l"(d) : "l"(a), "l"(b));
}
__device__ __forceinline__ float ex2(float x){
    float r; asm("ex2.approx.f32 %0,%1;" : "=f"(r) : "f"(x)); return r;
}
__device__ __forceinline__ float frcp(float x){
    float r; asm("rcp.approx.f32 %0,%1;" : "=f"(r) : "f"(x)); return r;
}

// per-CTA partials: [bh*4 + q4] slices
__device__ float g_Mp[512 * 4096];
__device__ float g_Sp[512 * 64];

// cT = log2(e) / softplus(delta)
__device__ __forceinline__ float get_cT(const float* __restrict__ delta){
    float d = delta[0];
    float t = (d > 20.f) ? d : log1pf(expf(d));
    return 1.44269504088896f / t;
}

#define BAR_PAIR(id) asm volatile("bar.sync %0, 64;" :: "r"(id) : "memory")

// =====================================================================
// Kernel 1: partial KV[d][e] and s[d] per (bh, quarter-of-L).
// grid 512, block 128 = 2 pairs of warps. Pair owns 512 rows as 16 tiles.
// Phase C v reads are LDS.128 via ulonglong2 (.x/.y feed fma2 directly).
// =====================================================================
__global__ __launch_bounds__(128, 4) void kv_kernel(
    const float* __restrict__ Kp, const float* __restrict__ Vp,
    const float* __restrict__ delta)
{
    __shared__ float pool[8832];   // k tiles [0,4352), v tiles [4352,8704), rs [8704,8768)

    const int bx   = blockIdx.x;
    const int bh   = bx >> 2;
    const int q4   = bx & 3;
    const int b    = bh >> 4, h = bh & 15;
    const int tid  = threadIdx.x;
    const int w    = tid >> 5, lane = tid & 31;
    const int pair = w >> 1, half = w & 1;
    const int eoff = half * 32;

    float* skt = pool + pair * 2176;
    float* svt = pool + 4352 + pair * 2176;
    float* sgp = pool + 8704 + pair * 32;

    const float cT = get_cT(delta);

    const long cbase = ((long)b * 4096L) * 1024L + h * 64L;
    const float* kb = Kp + cbase;
    const float* vb = Vp + cbase;

    u64 accA[16], accB[16];
    #pragma unroll
    for (int j = 0; j < 16; j++){ accA[j] = 0ull; accB[j] = 0ull; }
    float s0 = 0.f, s1 = 0.f;

    const int r_ld = lane >> 4;
    const int c_ld = (lane & 15) * 4;

    for (int t = 0; t < 16; t++){
        const long l0 = (long)q4 * 1024 + (long)pair * 512 + t * 32;

        // ---- Phase A: half0 loads k tile, half1 loads v tile ----
        {
            const float* src = half ? vb : kb;
            float* dst = half ? svt : skt;
            #pragma unroll
            for (int i = 0; i < 16; i++){
                const int r = 2 * i + r_ld;
                float4 v4 = *(const float4*)(src + (l0 + r) * 1024 + c_ld);
                *(float4*)(dst + r * 68 + c_ld) = v4;
            }
        }
        BAR_PAIR(1 + pair);

        // ---- Phase B: exp in place; rs per row (2 lanes/row, 1 shfl) ----
        {
            const int r  = half * 16 + (lane >> 1);
            float* rowp = skt + r * 68 + (lane & 1) * 32;
            float smA = 0.f, smB = 0.f;
            #pragma unroll
            for (int c = 0; c < 8; c++){
                float4 f = *(float4*)(rowp + 4 * c);
                f.x = ex2(cT * ((f.x < 0.f) ? -20.f : f.x));
                f.y = ex2(cT * ((f.y < 0.f) ? -20.f : f.y));
                f.z = ex2(cT * ((f.z < 0.f) ? -20.f : f.z));
                f.w = ex2(cT * ((f.w < 0.f) ? -20.f : f.w));
                *(float4*)(rowp + 4 * c) = f;
                smA += f.x + f.y; smB += f.z + f.w;
            }
            float sm = smA + smB;
            sm += __shfl_xor_sync(FULL, sm, 1);
            if ((lane & 1) == 0) sgp[r] = frcp(sm);
        }
        BAR_PAIR(1 + pair);

        // ---- Phase C: acc[d][e] += k''[d]*v[e]; LDS.128 v, no repack ----
        #pragma unroll 4
        for (int r = 0; r < 32; r++){
            float2 kp = *(const float2*)(skt + r * 68 + 2 * lane);
            float rs = sgp[r];
            float k0 = kp.x * rs, k1 = kp.y * rs;
            const u64 kk0 = pk2(k0, k0), kk1 = pk2(k1, k1);
            s0 += k0; s1 += k1;
            const ulonglong2* vrow2 = (const ulonglong2*)(svt + r * 68 + eoff);
            #pragma unroll
            for (int j2 = 0; j2 < 8; j2++){
                ulonglong2 vv = vrow2[j2];          // LDS.128 broadcast
                fma2(accA[2*j2],   kk0, vv.x); fma2(accA[2*j2+1], kk0, vv.y);
                fma2(accB[2*j2],   kk1, vv.x); fma2(accB[2*j2+1], kk1, vv.y);
            }
        }
        BAR_PAIR(1 + pair);
    }

    // ---- combine pairs in smem, write per-CTA partial ----
    __syncthreads();
    float* sM  = pool;            // 64 x 66
    float* sSh = pool + 4224;
    const int d0 = 2 * lane, d1 = d0 + 1;
    if (pair == 0){
        #pragma unroll
        for (int j = 0; j < 16; j++){
            *(float2*)&sM[d0 * 66 + eoff + 2 * j] = upk2(accA[j]);
            *(float2*)&sM[d1 * 66 + eoff + 2 * j] = upk2(accB[j]);
        }
        if (half == 0){ sSh[d0] = s0; sSh[d1] = s1; }
    }
    __syncthreads();
    if (pair == 1){
        #pragma unroll
        for (int j = 0; j < 16; j++){
            float2 a = upk2(accA[j]);
            float2 c0 = *(float2*)&sM[d0 * 66 + eoff + 2 * j];
            c0.x += a.x; c0.y += a.y;
            *(float2*)&sM[d0 * 66 + eoff + 2 * j] = c0;
            float2 c = upk2(accB[j]);
            float2 c1 = *(float2*)&sM[d1 * 66 + eoff + 2 * j];
            c1.x += c.x; c1.y += c.y;
            *(float2*)&sM[d1 * 66 + eoff + 2 * j] = c1;
        }
        if (half == 0){ sSh[d0] += s0; sSh[d1] += s1; }
    }
    __syncthreads();
    float* Mout = g_Mp + (long)bx * 4096;
    for (int i = tid; i < 4096; i += 128)
        Mout[i] = sM[(i >> 6) * 66 + (i & 63)];
    if (tid < 64) g_Sp[bx * 64 + tid] = sSh[tid];
}

// =====================================================================
// Kernel 2: out[l] = g_l * (E_l @ M). grid (128 bh, 3), block 128 =
// 4 INDEPENDENT warps (syncwarp only). Warp streams 32-row tiles strided
// by 12. Lane owns output e-pair; M register-resident (128 regs).
// Phase C q broadcasts are LDS.128 via ulonglong2 (no repack MOVs).
// =====================================================================
__global__ __launch_bounds__(128, 3) void out_kernel(
    const float* __restrict__ Qp, float* __restrict__ Out,
    const float* __restrict__ delta)
{
    __shared__ float sq[4][2176];
    __shared__ float sg[4][32];
    __shared__ float sSh[64];

    const int bh   = blockIdx.x;
    const int b    = bh >> 4, h = bh & 15;
    const int ck   = blockIdx.y;
    const int tid  = threadIdx.x;
    const int w    = tid >> 5, lane = tid & 31;

    const float cT = get_cT(delta);

    if (tid < 64){
        float s = 0.f;
        #pragma unroll
        for (int p = 0; p < 4; p++) s += g_Sp[(bh * 4 + p) * 64 + tid];
        sSh[tid] = s;
    }
    __syncthreads();

    // register M, partial-summed, paired along d
    u64 MA[32], MB[32];
    {
        const float* mp = g_Mp + (long)bh * 4 * 4096 + 2 * lane;
        #pragma unroll
        for (int j = 0; j < 32; j++){
            float2 r0 = make_float2(0.f, 0.f), r1 = make_float2(0.f, 0.f);
            #pragma unroll
            for (int p = 0; p < 4; p++){
                float2 a = *(const float2*)(mp + p * 4096 + (2 * j) * 64);
                float2 c = *(const float2*)(mp + p * 4096 + (2 * j + 1) * 64);
                r0.x += a.x; r0.y += a.y; r1.x += c.x; r1.y += c.y;
            }
            MA[j] = pk2(r0.x, r1.x);   // (M[2j][e0], M[2j+1][e0])
            MB[j] = pk2(r0.y, r1.y);   // (M[2j][e1], M[2j+1][e1])
        }
    }

    float* sqw = sq[w];
    const long cbase = ((long)b * 4096L) * 1024L + h * 64L;
    const int r_ld = lane >> 4;
    const int c_ld = (lane & 15) * 4;

    for (int t = ck * 4 + w; t < 128; t += 12){
        const long l0 = (long)t * 32;

        // ---- Phase A: coalesced tile load ----
        #pragma unroll
        for (int i = 0; i < 16; i++){
            const int r = 2 * i + r_ld;
            float4 v4 = *(const float4*)(Qp + cbase + (l0 + r) * 1024 + c_ld);
            *(float4*)(sqw + r * 68 + c_ld) = v4;
        }
        __syncwarp();

        // ---- Phase B: lane-per-row exp + sums, no shuffles ----
        {
            float* rowp = sqw + lane * 68;
            float sm0 = 0.f, sm1 = 0.f, u0 = 0.f, u1 = 0.f;
            #pragma unroll
            for (int c = 0; c < 16; c++){
                float4 f = *(float4*)(rowp + 4 * c);
                float4 s4 = *(const float4*)(sSh + 4 * c);   // broadcast
                f.x = ex2(cT * ((f.x < 0.f) ? -20.f : f.x));
                f.y = ex2(cT * ((f.y < 0.f) ? -20.f : f.y));
                f.z = ex2(cT * ((f.z < 0.f) ? -20.f : f.z));
                f.w = ex2(cT * ((f.w < 0.f) ? -20.f : f.w));
                *(float4*)(rowp + 4 * c) = f;
                sm0 += f.x + f.y;        sm1 += f.z + f.w;
                u0 = fmaf(f.x, s4.x, fmaf(f.y, s4.y, u0));
                u1 = fmaf(f.z, s4.z, fmaf(f.w, s4.w, u1));
            }
            sg[w][lane] = frcp((u0 + u1) + 1e-6f * (sm0 + sm1));
        }
        __syncwarp();

        // ---- Phase C: matvec per row; LDS.128 q broadcasts, no repack ----
        #pragma unroll 2
        for (int r = 0; r < 32; r++){
            const ulonglong2* qr2 = (const ulonglong2*)(sqw + r * 68);
            u64 oA = 0ull, oB = 0ull;
            #pragma unroll
            for (int j = 0; j < 16; j++){
                ulonglong2 qp = qr2[j];             // LDS.128 broadcast
                fma2(oA, qp.x, MA[2 * j]);
                fma2(oB, qp.x, MB[2 * j]);
                fma2(oA, qp.y, MA[2 * j + 1]);
                fma2(oB, qp.y, MB[2 * j + 1]);
            }
            float g = sg[w][r];
            float2 A = upk2(oA), Bv = upk2(oB);
            *(float2*)(Out + cbase + (l0 + r) * 1024 + 2 * lane)
                = make_float2((A.x + A.y) * g, (Bv.x + Bv.y) * g);
        }
        __syncwarp();
    }
}

extern "C" void kernel_launch(void* const* d_in, const int* in_sizes, int n_in,
                              void* d_out, int out_size)
{
    const float* Q     = (const float*)d_in[0];
    const float* K     = (const float*)d_in[1];
    const float* V     = (const float*)d_in[2];
    const float* delta = (const float*)d_in[3];
    float* Out = (float*)d_out;

    kv_kernel<<<512, 128>>>(K, V, delta);
    out_kernel<<<dim3(128, 3), 128>>>(Q, Out, delta);
}

// round 7
// speedup vs baseline: 1.2055x; 1.0162x over previous
#include <cuda_runtime.h>
#include <cstdint>

typedef unsigned long long u64;
#define FULL 0xFFFFFFFFu

__device__ __forceinline__ u64 pk2(float x, float y){
    u64 r; asm("mov.b64 %0,{%1,%2};" : "=l"(r) : "f"(x), "f"(y)); return r;
}
__device__ __forceinline__ float2 upk2(u64 a){
    float2 r; asm("mov.b64 {%0,%1},%2;" : "=f"(r.x), "=f"(r.y) : "l"(a)); return r;
}
__device__ __forceinline__ void fma2(u64 &d, u64 a, u64 b){
    asm("fma.rn.f32x2 %0,%1,%2,%0;" : "+l"(d) : "l"(a), "l"(b));
}
__device__ __forceinline__ float ex2(float x){
    float r; asm("ex2.approx.f32 %0,%1;" : "=f"(r) : "f"(x)); return r;
}
__device__ __forceinline__ float frcp(float x){
    float r; asm("rcp.approx.f32 %0,%1;" : "=f"(r) : "f"(x)); return r;
}
__device__ __forceinline__ void cpa16(uint32_t dst, const void* src){
    asm volatile("cp.async.cg.shared.global [%0], [%1], 16;" :: "r"(dst), "l"(src));
}
__device__ __forceinline__ void cp_commit(){ asm volatile("cp.async.commit_group;"); }
__device__ __forceinline__ void cp_wait1(){ asm volatile("cp.async.wait_group 1;"); }
__device__ __forceinline__ void cp_wait0(){ asm volatile("cp.async.wait_group 0;"); }

// per-CTA partials: [bh*4 + q4] slices
__device__ float g_Mp[512 * 4096];
__device__ float g_Sp[512 * 64];

// cT = log2(e) / softplus(delta)
__device__ __forceinline__ float get_cT(const float* __restrict__ delta){
    float d = delta[0];
    float t = (d > 20.f) ? d : log1pf(expf(d));
    return 1.44269504088896f / t;
}

#define BAR_PAIR(id) asm volatile("bar.sync %0, 64;" :: "r"(id) : "memory")

// =====================================================================
// Kernel 1: partial KV[d][e], s[d] per (bh, quarter-of-L). grid 512,
// block 128 = 2 pairs. Pair owns 512 rows as 32 double-buffered 16-row
// tiles streamed via cp.async (half0 warp: k, half1 warp: v).
// =====================================================================
__global__ __launch_bounds__(128, 4) void kv_kernel(
    const float* __restrict__ Kp, const float* __restrict__ Vp,
    const float* __restrict__ delta)
{
    __shared__ float pool[8768];   // k: pair*2176 (2x1088), v: 4352+pair*2176, sgp: 8704+pair*16

    const int bx   = blockIdx.x;
    const int bh   = bx >> 2;
    const int q4   = bx & 3;
    const int b    = bh >> 4, h = bh & 15;
    const int tid  = threadIdx.x;
    const int w    = tid >> 5, lane = tid & 31;
    const int pair = w >> 1, half = w & 1;
    const int eoff = half * 32;

    float* skp = pool + pair * 2176;
    float* svp = pool + 4352 + pair * 2176;
    float* sgp = pool + 8704 + pair * 16;

    const float cT = get_cT(delta);

    const long cbase = ((long)b * 4096L) * 1024L + h * 64L;
    const float* kb = Kp + cbase;
    const float* vb = Vp + cbase;
    const long lbase = (long)q4 * 1024 + (long)pair * 512;

    const uint32_t my_dst = (uint32_t)__cvta_generic_to_shared(half ? svp : skp);
    const float*   my_src = half ? vb : kb;

    u64 accA[16], accB[16];
    #pragma unroll
    for (int j = 0; j < 16; j++){ accA[j] = 0ull; accB[j] = 0ull; }
    float s0 = 0.f, s1 = 0.f;

    // prologue: issue tile 0 into buf 0
    {
        #pragma unroll
        for (int i = 0; i < 8; i++){
            const int c = lane + 32 * i;
            const int r = c >> 4, col = (c & 15) * 4;
            cpa16(my_dst + (r * 68 + col) * 4, my_src + (lbase + r) * 1024 + col);
        }
        cp_commit();
    }

    int buf = 0;
    for (int t = 0; t < 32; t++){
        if (t + 1 < 32){
            const long l0 = lbase + (long)(t + 1) * 16;
            const uint32_t du = my_dst + (buf ^ 1) * 1088 * 4;
            #pragma unroll
            for (int i = 0; i < 8; i++){
                const int c = lane + 32 * i;
                const int r = c >> 4, col = (c & 15) * 4;
                cpa16(du + (r * 68 + col) * 4, my_src + (l0 + r) * 1024 + col);
            }
            cp_commit();
            cp_wait1();
        } else {
            cp_wait0();
        }
        BAR_PAIR(1 + pair);

        float* skb = skp + buf * 1088;
        float* svb = svp + buf * 1088;

        // ---- Phase B: exp in place; 4 lanes/row, 8 rows per warp ----
        {
            const int r = half * 8 + (lane >> 2);
            const int q = lane & 3;
            float* rowp = skb + r * 68 + q * 16;
            float sm = 0.f;
            #pragma unroll
            for (int c = 0; c < 4; c++){
                float4 f = *(float4*)(rowp + 4 * c);
                f.x = ex2(cT * ((f.x < 0.f) ? -20.f : f.x));
                f.y = ex2(cT * ((f.y < 0.f) ? -20.f : f.y));
                f.z = ex2(cT * ((f.z < 0.f) ? -20.f : f.z));
                f.w = ex2(cT * ((f.w < 0.f) ? -20.f : f.w));
                *(float4*)(rowp + 4 * c) = f;
                sm += (f.x + f.y) + (f.z + f.w);
            }
            sm += __shfl_xor_sync(FULL, sm, 1);
            sm += __shfl_xor_sync(FULL, sm, 2);
            if (q == 0) sgp[r] = frcp(sm);
        }
        BAR_PAIR(1 + pair);

        // ---- Phase C: acc[d][e] += k''[d] * v[e] over 16 rows ----
        #pragma unroll 4
        for (int r = 0; r < 16; r++){
            float2 kp = *(const float2*)(skb + r * 68 + 2 * lane);
            float rs = sgp[r];
            float k0 = kp.x * rs, k1 = kp.y * rs;
            const u64 kk0 = pk2(k0, k0), kk1 = pk2(k1, k1);
            s0 += k0; s1 += k1;
            const ulonglong2* vrow2 = (const ulonglong2*)(svb + r * 68 + eoff);
            #pragma unroll
            for (int j2 = 0; j2 < 8; j2++){
                ulonglong2 vv = vrow2[j2];
                fma2(accA[2*j2],   kk0, vv.x); fma2(accA[2*j2+1], kk0, vv.y);
                fma2(accB[2*j2],   kk1, vv.x); fma2(accB[2*j2+1], kk1, vv.y);
            }
        }
        BAR_PAIR(1 + pair);
        buf ^= 1;
    }

    // ---- combine pairs in smem (alias pool), write per-CTA partial ----
    __syncthreads();
    float* sM  = pool;            // 64 x 66
    float* sSh = pool + 4224;
    const int d0 = 2 * lane, d1 = d0 + 1;
    if (pair == 0){
        #pragma unroll
        for (int j = 0; j < 16; j++){
            *(float2*)&sM[d0 * 66 + eoff + 2 * j] = upk2(accA[j]);
            *(float2*)&sM[d1 * 66 + eoff + 2 * j] = upk2(accB[j]);
        }
        if (half == 0){ sSh[d0] = s0; sSh[d1] = s1; }
    }
    __syncthreads();
    if (pair == 1){
        #pragma unroll
        for (int j = 0; j < 16; j++){
            float2 a = upk2(accA[j]);
            float2 c0 = *(float2*)&sM[d0 * 66 + eoff + 2 * j];
            c0.x += a.x; c0.y += a.y;
            *(float2*)&sM[d0 * 66 + eoff + 2 * j] = c0;
            float2 c = upk2(accB[j]);
            float2 c1 = *(float2*)&sM[d1 * 66 + eoff + 2 * j];
            c1.x += c.x; c1.y += c.y;
            *(float2*)&sM[d1 * 66 + eoff + 2 * j] = c1;
        }
        if (half == 0){ sSh[d0] += s0; sSh[d1] += s1; }
    }
    __syncthreads();
    float* Mout = g_Mp + (long)bx * 4096;
    for (int i = tid; i < 4096; i += 128)
        Mout[i] = sM[(i >> 6) * 66 + (i & 63)];
    if (tid < 64) g_Sp[bx * 64 + tid] = sSh[tid];
}

// =====================================================================
// Kernel 2: out[l] = g_l * (E_l @ M). grid (128 bh, 3), block 128 =
// 4 INDEPENDENT warps. Warp streams 16-row tiles (stride 12) with
// cp.async double buffering. Lane owns output e-pair; M in 128 regs;
// 4 accumulator chains per row.
// =====================================================================
__global__ __launch_bounds__(128, 3) void out_kernel(
    const float* __restrict__ Qp, float* __restrict__ Out,
    const float* __restrict__ delta)
{
    __shared__ float sq[4][2][1088];
    __shared__ float sg[4][16];
    __shared__ float sSh[64];

    const int bh   = blockIdx.x;
    const int b    = bh >> 4, h = bh & 15;
    const int ck   = blockIdx.y;
    const int tid  = threadIdx.x;
    const int w    = tid >> 5, lane = tid & 31;

    const float cT = get_cT(delta);

    if (tid < 64){
        float s = 0.f;
        #pragma unroll
        for (int p = 0; p < 4; p++) s += g_Sp[(bh * 4 + p) * 64 + tid];
        sSh[tid] = s;
    }
    __syncthreads();

    // register M, partial-summed, paired along d
    u64 MA[32], MB[32];
    {
        const float* mp = g_Mp + (long)bh * 4 * 4096 + 2 * lane;
        #pragma unroll
        for (int j = 0; j < 32; j++){
            float2 r0 = make_float2(0.f, 0.f), r1 = make_float2(0.f, 0.f);
            #pragma unroll
            for (int p = 0; p < 4; p++){
                float2 a = *(const float2*)(mp + p * 4096 + (2 * j) * 64);
                float2 c = *(const float2*)(mp + p * 4096 + (2 * j + 1) * 64);
                r0.x += a.x; r0.y += a.y; r1.x += c.x; r1.y += c.y;
            }
            MA[j] = pk2(r0.x, r1.x);
            MB[j] = pk2(r0.y, r1.y);
        }
    }

    const long cbase = ((long)b * 4096L) * 1024L + h * 64L;
    const uint32_t squ = (uint32_t)__cvta_generic_to_shared(&sq[w][0][0]);

    const int t0 = ck * 4 + w;
    // prologue: issue tile t0 into buf 0
    {
        const long l0 = (long)t0 * 16;
        #pragma unroll
        for (int i = 0; i < 8; i++){
            const int c = lane + 32 * i;
            const int r = c >> 4, col = (c & 15) * 4;
            cpa16(squ + (r * 68 + col) * 4, Qp + cbase + (l0 + r) * 1024 + col);
        }
        cp_commit();
    }

    int buf = 0;
    for (int t = t0; t < 256; t += 12){
        const int tn = t + 12;
        if (tn < 256){
            const long l0 = (long)tn * 16;
            const uint32_t du = squ + (buf ^ 1) * 1088 * 4;
            #pragma unroll
            for (int i = 0; i < 8; i++){
                const int c = lane + 32 * i;
                const int r = c >> 4, col = (c & 15) * 4;
                cpa16(du + (r * 68 + col) * 4, Qp + cbase + (l0 + r) * 1024 + col);
            }
            cp_commit();
            cp_wait1();
        } else {
            cp_wait0();
        }
        __syncwarp();

        float* bq = &sq[w][buf][0];

        // ---- Phase B: exp + row sums; 2 lanes/row over 16 rows ----
        {
            const int r = lane >> 1, h32 = (lane & 1) * 32;
            float* rowp = bq + r * 68 + h32;
            const float* sp = sSh + h32;
            float sm = 0.f, u = 0.f;
            #pragma unroll
            for (int c = 0; c < 8; c++){
                float4 f = *(float4*)(rowp + 4 * c);
                float4 s4 = *(const float4*)(sp + 4 * c);
                f.x = ex2(cT * ((f.x < 0.f) ? -20.f : f.x));
                f.y = ex2(cT * ((f.y < 0.f) ? -20.f : f.y));
                f.z = ex2(cT * ((f.z < 0.f) ? -20.f : f.z));
                f.w = ex2(cT * ((f.w < 0.f) ? -20.f : f.w));
                *(float4*)(rowp + 4 * c) = f;
                sm += (f.x + f.y) + (f.z + f.w);
                u = fmaf(f.x, s4.x, fmaf(f.y, s4.y, fmaf(f.z, s4.z, fmaf(f.w, s4.w, u))));
            }
            sm += __shfl_xor_sync(FULL, sm, 1);
            u  += __shfl_xor_sync(FULL, u,  1);
            if ((lane & 1) == 0) sg[w][r] = frcp(u + 1e-6f * sm);
        }
        __syncwarp();

        // ---- Phase C: matvec per row; 4 chains, 16 deep each ----
        const long l0 = (long)t * 16;
        #pragma unroll 2
        for (int r = 0; r < 16; r++){
            const ulonglong2* qr2 = (const ulonglong2*)(bq + r * 68);
            u64 oA0 = 0ull, oA1 = 0ull, oB0 = 0ull, oB1 = 0ull;
            #pragma unroll
            for (int j = 0; j < 8; j++){
                ulonglong2 qa = qr2[2 * j];
                ulonglong2 qb = qr2[2 * j + 1];
                fma2(oA0, qa.x, MA[4*j]);   fma2(oB0, qa.x, MB[4*j]);
                fma2(oA1, qa.y, MA[4*j+1]); fma2(oB1, qa.y, MB[4*j+1]);
                fma2(oA0, qb.x, MA[4*j+2]); fma2(oB0, qb.x, MB[4*j+2]);
                fma2(oA1, qb.y, MA[4*j+3]); fma2(oB1, qb.y, MB[4*j+3]);
            }
            float g = sg[w][r];
            float2 A0 = upk2(oA0), A1 = upk2(oA1);
            float2 B0 = upk2(oB0), B1 = upk2(oB1);
            *(float2*)(Out + cbase + (l0 + r) * 1024 + 2 * lane)
                = make_float2(((A0.x + A0.y) + (A1.x + A1.y)) * g,
                              ((B0.x + B0.y) + (B1.x + B1.y)) * g);
        }
        __syncwarp();
        buf ^= 1;
    }
}

extern "C" void kernel_launch(void* const* d_in, const int* in_sizes, int n_in,
                              void* d_out, int out_size)
{
    const float* Q     = (const float*)d_in[0];
    const float* K     = (const float*)d_in[1];
    const float* V     = (const float*)d_in[2];
    const float* delta = (const float*)d_in[3];
    float* Out = (float*)d_out;

    kv_kernel<<<512, 128>>>(K, V, delta);
    out_kernel<<<dim3(128, 3), 128>>>(Q, Out, delta);
}

// round 9
// speedup vs baseline: 1.5801x; 1.3107x over previous
#include <cuda_runtime.h>
#include <cstdint>

typedef unsigned long long u64;
typedef unsigned int u32;
#define FULL 0xFFFFFFFFu

__device__ __forceinline__ u64 pk2(float x, float y){
    u64 r; asm("mov.b64 %0,{%1,%2};" : "=l"(r) : "f"(x), "f"(y)); return r;
}
__device__ __forceinline__ float2 upk2(u64 a){
    float2 r; asm("mov.b64 {%0,%1},%2;" : "=f"(r.x), "=f"(r.y) : "l"(a)); return r;
}
__device__ __forceinline__ void fma2(u64 &d, u64 a, u64 b){
    asm("fma.rn.f32x2 %0,%1,%2,%0;" : "+l"(d) : "l"(a), "l"(b));
}
__device__ __forceinline__ float ex2(float x){
    float r; asm("ex2.approx.f32 %0,%1;" : "=f"(r) : "f"(x)); return r;
}
__device__ __forceinline__ float frcp(float x){
    float r; asm("rcp.approx.f32 %0,%1;" : "=f"(r) : "f"(x)); return r;
}
__device__ __forceinline__ u32 totf32(float x){
    u32 r; asm("cvt.rna.tf32.f32 %0,%1;" : "=r"(r) : "f"(x)); return r;
}
__device__ __forceinline__ void cpa16(u32 dst, const void* src){
    asm volatile("cp.async.cg.shared.global [%0], [%1], 16;" :: "r"(dst), "l"(src));
}
__device__ __forceinline__ void cp_commit(){ asm volatile("cp.async.commit_group;"); }
__device__ __forceinline__ void cp_wait1(){ asm volatile("cp.async.wait_group 1;"); }
__device__ __forceinline__ void cp_wait0(){ asm volatile("cp.async.wait_group 0;"); }

// per-CTA partials: [bh*4 + q4]
__device__ float g_Mp[512 * 4096];
__device__ float g_Sp[512 * 64];

__device__ __forceinline__ float get_cT(const float* __restrict__ delta){
    float d = delta[0];
    float t = (d > 20.f) ? d : log1pf(expf(d));
    return 1.44269504088896f / t;
}

#define MMA_TF32(C, a0,a1,a2,a3, b0,b1) \
    asm("mma.sync.aligned.m16n8k8.row.col.f32.tf32.tf32.f32 " \
        "{%0,%1,%2,%3},{%4,%5,%6,%7},{%8,%9},{%0,%1,%2,%3};" \
        : "+f"((C)[0]),"+f"((C)[1]),"+f"((C)[2]),"+f"((C)[3]) \
        : "r"(a0),"r"(a1),"r"(a2),"r"(a3), "r"(b0),"r"(b1))

// =====================================================================
// kv_mma: partial KV[64][64] + s[64] per (bh, quarter-of-L) via tf32 MMA.
// grid 512, block 128. CTA owns 1024 L-rows = 64 tiles of 16, double-
// buffered via cp.async. Tile layout: [16 rows][72 floats] (k and v).
// Phase B: softmax lane-per-(row/8th), rs folded in, stored as tf32 bits.
// Phase C: warp w owns e-cols [16w,16w+16); warp 3 also owns the ones
// column at e=64 giving D[d][64] = s[d].
// =====================================================================
__global__ __launch_bounds__(128, 4) void kv_mma(
    const float* __restrict__ Kp, const float* __restrict__ Vp,
    const float* __restrict__ delta)
{
    __shared__ float pool[4608];   // k: [buf*1152], v: 2304 + buf*1152

    const int bx   = blockIdx.x;
    const int bh   = bx >> 2;
    const int b    = bh >> 4, h = bh & 15;
    const int tid  = threadIdx.x;
    const int w    = tid >> 5, lane = tid & 31;
    const int g    = lane >> 2, tig = lane & 3;

    const float cT = get_cT(delta);
    const long cbase = ((long)b * 4096L) * 1024L + h * 64L;
    const float* kglob = Kp + cbase;
    const float* vglob = Vp + cbase;
    const long Lbase = (long)(bx & 3) * 1024;

    const u32 sb = (u32)__cvta_generic_to_shared(pool);

    // ones column at e=64 (cols 65-71 zero) in both v buffers
    for (int idx = tid; idx < 256; idx += 128){
        int buf = idx >> 7, rem = idx & 127;
        int row = rem >> 3, col = 64 + (rem & 7);
        pool[2304 + buf * 1152 + row * 72 + col] = (col == 64) ? 1.f : 0.f;
    }
    __syncthreads();

    // accumulators: C[mt][nt][4]; nt=2 only live for warp 3 (s column)
    float C[4][3][4];
    #pragma unroll
    for (int mt = 0; mt < 4; mt++)
        #pragma unroll
        for (int nt = 0; nt < 3; nt++)
            #pragma unroll
            for (int i = 0; i < 4; i++) C[mt][nt][i] = 0.f;
    const int nts = (w == 3) ? 3 : 2;
    const int e0  = w * 16;

    auto load_tile = [&](int t, int buf){
        const long l0 = Lbase + (long)t * 16;
        const float* src = (w < 2) ? kglob : vglob;
        const u32 dbase = sb + ((w < 2 ? 0 : 2304) + buf * 1152) * 4;
        #pragma unroll
        for (int i = 0; i < 4; i++){
            int slot = lane + 32 * i;          // 0..127
            int r = (w & 1) * 8 + (slot >> 4); // 0..15
            int ch = slot & 15;
            cpa16(dbase + (u32)(r * 72 + ch * 4) * 4, src + (l0 + r) * 1024 + ch * 4);
        }
        cp_commit();
    };

    load_tile(0, 0);

    int buf = 0;
    for (int t = 0; t < 64; t++){
        if (t + 1 < 64){ load_tile(t + 1, buf ^ 1); cp_wait1(); }
        else cp_wait0();
        __syncthreads();

        float* kbuf = pool + buf * 1152;
        const float* vbuf = pool + 2304 + buf * 1152;

        // ---- Phase B: softmax, rs folded, store tf32 bits in place ----
        {
            const int row = tid >> 3, sub = tid & 7;
            float* rowp = kbuf + row * 72 + sub * 8;
            float4 fa = *(float4*)rowp;
            float4 fb = *(float4*)(rowp + 4);
            float v0 = ex2(cT * ((fa.x < 0.f) ? -20.f : fa.x));
            float v1 = ex2(cT * ((fa.y < 0.f) ? -20.f : fa.y));
            float v2 = ex2(cT * ((fa.z < 0.f) ? -20.f : fa.z));
            float v3 = ex2(cT * ((fa.w < 0.f) ? -20.f : fa.w));
            float v4 = ex2(cT * ((fb.x < 0.f) ? -20.f : fb.x));
            float v5 = ex2(cT * ((fb.y < 0.f) ? -20.f : fb.y));
            float v6 = ex2(cT * ((fb.z < 0.f) ? -20.f : fb.z));
            float v7 = ex2(cT * ((fb.w < 0.f) ? -20.f : fb.w));
            float sm = ((v0 + v1) + (v2 + v3)) + ((v4 + v5) + (v6 + v7));
            sm += __shfl_xor_sync(FULL, sm, 1);
            sm += __shfl_xor_sync(FULL, sm, 2);
            sm += __shfl_xor_sync(FULL, sm, 4);
            float rs = frcp(sm);
            uint4 oa, ob;
            oa.x = totf32(v0 * rs); oa.y = totf32(v1 * rs);
            oa.z = totf32(v2 * rs); oa.w = totf32(v3 * rs);
            ob.x = totf32(v4 * rs); ob.y = totf32(v5 * rs);
            ob.z = totf32(v6 * rs); ob.w = totf32(v7 * rs);
            *(uint4*)rowp = oa;
            *(uint4*)(rowp + 4) = ob;
        }
        __syncthreads();

        // ---- Phase C: tf32 MMA over this 16-row tile ----
        {
            const u32* kB = (const u32*)kbuf;
            u32 bf[2][3][2];
            #pragma unroll
            for (int kt = 0; kt < 2; kt++)
                #pragma unroll
                for (int nt = 0; nt < 3; nt++)
                    if (nt < nts){
                        float b0 = vbuf[(kt * 8 + tig) * 72 + e0 + nt * 8 + g];
                        float b1 = vbuf[(kt * 8 + tig + 4) * 72 + e0 + nt * 8 + g];
                        bf[kt][nt][0] = totf32(b0);
                        bf[kt][nt][1] = totf32(b1);
                    }
            #pragma unroll
            for (int mt = 0; mt < 4; mt++){
                #pragma unroll
                for (int kt = 0; kt < 2; kt++){
                    u32 a0 = kB[(kt * 8 + tig) * 72 + mt * 16 + g];
                    u32 a1 = kB[(kt * 8 + tig) * 72 + mt * 16 + g + 8];
                    u32 a2 = kB[(kt * 8 + tig + 4) * 72 + mt * 16 + g];
                    u32 a3 = kB[(kt * 8 + tig + 4) * 72 + mt * 16 + g + 8];
                    #pragma unroll
                    for (int nt = 0; nt < 3; nt++)
                        if (nt < nts) MMA_TF32(C[mt][nt], a0, a1, a2, a3,
                                               bf[kt][nt][0], bf[kt][nt][1]);
                }
            }
        }
        __syncthreads();
        buf ^= 1;
    }

    // ---- epilogue: scatter C fragments to per-CTA partials ----
    float* Mp = g_Mp + (long)bx * 4096;
    #pragma unroll
    for (int mt = 0; mt < 4; mt++){
        #pragma unroll
        for (int nt = 0; nt < 3; nt++){
            if (nt >= nts) continue;
            if (w == 3 && nt == 2){
                if (tig == 0){
                    g_Sp[bx * 64 + mt * 16 + g]     = C[mt][2][0];
                    g_Sp[bx * 64 + mt * 16 + g + 8] = C[mt][2][2];
                }
            } else {
                const int e = e0 + nt * 8 + 2 * tig;
                *(float2*)(Mp + (mt * 16 + g) * 64 + e)
                    = make_float2(C[mt][nt][0], C[mt][nt][1]);
                *(float2*)(Mp + (mt * 16 + g + 8) * 64 + e)
                    = make_float2(C[mt][nt][2], C[mt][nt][3]);
            }
        }
    }
}

// =====================================================================
// Kernel 2: out[l] = g_l * (E_l @ M) — proven R4/R7 structure, sums the
// 4 kv partials while building the register M.
// =====================================================================
__global__ __launch_bounds__(128, 3) void out_kernel(
    const float* __restrict__ Qp, float* __restrict__ Out,
    const float* __restrict__ delta)
{
    __shared__ float sq[4][2176];
    __shared__ float sg[4][32];
    __shared__ float sSh[64];

    const int bh   = blockIdx.x;
    const int b    = bh >> 4, h = bh & 15;
    const int ck   = blockIdx.y;
    const int tid  = threadIdx.x;
    const int w    = tid >> 5, lane = tid & 31;

    const float cT = get_cT(delta);

    if (tid < 64){
        float s = 0.f;
        #pragma unroll
        for (int p = 0; p < 4; p++) s += g_Sp[(bh * 4 + p) * 64 + tid];
        sSh[tid] = s;
    }
    __syncthreads();

    u64 MA[32], MB[32];
    {
        const float* mp = g_Mp + (long)bh * 4 * 4096 + 2 * lane;
        #pragma unroll
        for (int j = 0; j < 32; j++){
            float2 r0 = make_float2(0.f, 0.f), r1 = make_float2(0.f, 0.f);
            #pragma unroll
            for (int p = 0; p < 4; p++){
                float2 a = *(const float2*)(mp + p * 4096 + (2 * j) * 64);
                float2 c = *(const float2*)(mp + p * 4096 + (2 * j + 1) * 64);
                r0.x += a.x; r0.y += a.y; r1.x += c.x; r1.y += c.y;
            }
            MA[j] = pk2(r0.x, r1.x);
            MB[j] = pk2(r0.y, r1.y);
        }
    }

    float* sqw = sq[w];
    const long cbase = ((long)b * 4096L) * 1024L + h * 64L;
    const int r_ld = lane >> 4;
    const int c_ld = (lane & 15) * 4;

    for (int t = ck * 4 + w; t < 128; t += 12){
        const long l0 = (long)t * 32;

        #pragma unroll
        for (int i = 0; i < 16; i++){
            const int r = 2 * i + r_ld;
            float4 v4 = *(const float4*)(Qp + cbase + (l0 + r) * 1024 + c_ld);
            *(float4*)(sqw + r * 68 + c_ld) = v4;
        }
        __syncwarp();

        {
            float* rowp = sqw + lane * 68;
            float sm0 = 0.f, sm1 = 0.f, u0 = 0.f, u1 = 0.f;
            #pragma unroll
            for (int c = 0; c < 16; c++){
                float4 f = *(float4*)(rowp + 4 * c);
                float4 s4 = *(const float4*)(sSh + 4 * c);
                f.x = ex2(cT * ((f.x < 0.f) ? -20.f : f.x));
                f.y = ex2(cT * ((f.y < 0.f) ? -20.f : f.y));
                f.z = ex2(cT * ((f.z < 0.f) ? -20.f : f.z));
                f.w = ex2(cT * ((f.w < 0.f) ? -20.f : f.w));
                *(float4*)(rowp + 4 * c) = f;
                sm0 += f.x + f.y;        sm1 += f.z + f.w;
                u0 = fmaf(f.x, s4.x, fmaf(f.y, s4.y, u0));
                u1 = fmaf(f.z, s4.z, fmaf(f.w, s4.w, u1));
            }
            sg[w][lane] = frcp((u0 + u1) + 1e-6f * (sm0 + sm1));
        }
        __syncwarp();

        #pragma unroll 2
        for (int r = 0; r < 32; r++){
            const ulonglong2* qr2 = (const ulonglong2*)(sqw + r * 68);
            u64 oA = 0ull, oB = 0ull;
            #pragma unroll
            for (int j = 0; j < 16; j++){
                ulonglong2 qp = qr2[j];
                fma2(oA, qp.x, MA[2 * j]);
                fma2(oB, qp.x, MB[2 * j]);
                fma2(oA, qp.y, MA[2 * j + 1]);
                fma2(oB, qp.y, MB[2 * j + 1]);
            }
            float gv = sg[w][r];
            float2 A = upk2(oA), Bv = upk2(oB);
            *(float2*)(Out + cbase + (l0 + r) * 1024 + 2 * lane)
                = make_float2((A.x + A.y) * gv, (Bv.x + Bv.y) * gv);
        }
        __syncwarp();
    }
}

extern "C" void kernel_launch(void* const* d_in, const int* in_sizes, int n_in,
                              void* d_out, int out_size)
{
    const float* Q     = (const float*)d_in[0];
    const float* K     = (const float*)d_in[1];
    const float* V     = (const float*)d_in[2];
    const float* delta = (const float*)d_in[3];
    float* Out = (float*)d_out;

    kv_mma<<<512, 128>>>(K, V, delta);
    out_kernel<<<dim3(128, 3), 128>>>(Q, Out, delta);
}

// round 10
// speedup vs baseline: 1.9378x; 1.2264x over previous
#include <cuda_runtime.h>
#include <cstdint>

typedef unsigned long long u64;
typedef unsigned int u32;
#define FULL 0xFFFFFFFFu

__device__ __forceinline__ float ex2(float x){
    float r; asm("ex2.approx.f32 %0,%1;" : "=f"(r) : "f"(x)); return r;
}
__device__ __forceinline__ float frcp(float x){
    float r; asm("rcp.approx.f32 %0,%1;" : "=f"(r) : "f"(x)); return r;
}
__device__ __forceinline__ u32 totf32(float x){
    u32 r; asm("cvt.rna.tf32.f32 %0,%1;" : "=r"(r) : "f"(x)); return r;
}
__device__ __forceinline__ void cpa16(u32 dst, const void* src){
    asm volatile("cp.async.cg.shared.global [%0], [%1], 16;" :: "r"(dst), "l"(src));
}
__device__ __forceinline__ void cp_commit(){ asm volatile("cp.async.commit_group;"); }
__device__ __forceinline__ void cp_wait1(){ asm volatile("cp.async.wait_group 1;"); }
__device__ __forceinline__ void cp_wait0(){ asm volatile("cp.async.wait_group 0;"); }

// per-CTA partials: [bh*4 + q4]
__device__ float g_Mp[512 * 4096];
__device__ float g_Sp[512 * 64];

__device__ __forceinline__ float get_cT(const float* __restrict__ delta){
    float d = delta[0];
    float t = (d > 20.f) ? d : log1pf(expf(d));
    return 1.44269504088896f / t;
}

#define MMA_TF32(C, a0,a1,a2,a3, b0,b1) \
    asm("mma.sync.aligned.m16n8k8.row.col.f32.tf32.tf32.f32 " \
        "{%0,%1,%2,%3},{%4,%5,%6,%7},{%8,%9},{%0,%1,%2,%3};" \
        : "+f"((C)[0]),"+f"((C)[1]),"+f"((C)[2]),"+f"((C)[3]) \
        : "r"(a0),"r"(a1),"r"(a2),"r"(a3), "r"(b0),"r"(b1))

// =====================================================================
// kv_mma: partial KV[64][64] + s[64] per (bh, quarter-of-L) via tf32 MMA.
// (unchanged from round 9 — measured ~67us)
// =====================================================================
__global__ __launch_bounds__(128, 4) void kv_mma(
    const float* __restrict__ Kp, const float* __restrict__ Vp,
    const float* __restrict__ delta)
{
    __shared__ float pool[4608];   // k: [buf*1152], v: 2304 + buf*1152

    const int bx   = blockIdx.x;
    const int bh   = bx >> 2;
    const int b    = bh >> 4, h = bh & 15;
    const int tid  = threadIdx.x;
    const int w    = tid >> 5, lane = tid & 31;
    const int g    = lane >> 2, tig = lane & 3;

    const float cT = get_cT(delta);
    const long cbase = ((long)b * 4096L) * 1024L + h * 64L;
    const float* kglob = Kp + cbase;
    const float* vglob = Vp + cbase;
    const long Lbase = (long)(bx & 3) * 1024;

    const u32 sb = (u32)__cvta_generic_to_shared(pool);

    for (int idx = tid; idx < 256; idx += 128){
        int buf = idx >> 7, rem = idx & 127;
        int row = rem >> 3, col = 64 + (rem & 7);
        pool[2304 + buf * 1152 + row * 72 + col] = (col == 64) ? 1.f : 0.f;
    }
    __syncthreads();

    float C[4][3][4];
    #pragma unroll
    for (int mt = 0; mt < 4; mt++)
        #pragma unroll
        for (int nt = 0; nt < 3; nt++)
            #pragma unroll
            for (int i = 0; i < 4; i++) C[mt][nt][i] = 0.f;
    const int nts = (w == 3) ? 3 : 2;
    const int e0  = w * 16;

    auto load_tile = [&](int t, int buf){
        const long l0 = Lbase + (long)t * 16;
        const float* src = (w < 2) ? kglob : vglob;
        const u32 dbase = sb + ((w < 2 ? 0 : 2304) + buf * 1152) * 4;
        #pragma unroll
        for (int i = 0; i < 4; i++){
            int slot = lane + 32 * i;
            int r = (w & 1) * 8 + (slot >> 4);
            int ch = slot & 15;
            cpa16(dbase + (u32)(r * 72 + ch * 4) * 4, src + (l0 + r) * 1024 + ch * 4);
        }
        cp_commit();
    };

    load_tile(0, 0);

    int buf = 0;
    for (int t = 0; t < 64; t++){
        if (t + 1 < 64){ load_tile(t + 1, buf ^ 1); cp_wait1(); }
        else cp_wait0();
        __syncthreads();

        float* kbuf = pool + buf * 1152;
        const float* vbuf = pool + 2304 + buf * 1152;

        {
            const int row = tid >> 3, sub = tid & 7;
            float* rowp = kbuf + row * 72 + sub * 8;
            float4 fa = *(float4*)rowp;
            float4 fb = *(float4*)(rowp + 4);
            float v0 = ex2(cT * ((fa.x < 0.f) ? -20.f : fa.x));
            float v1 = ex2(cT * ((fa.y < 0.f) ? -20.f : fa.y));
            float v2 = ex2(cT * ((fa.z < 0.f) ? -20.f : fa.z));
            float v3 = ex2(cT * ((fa.w < 0.f) ? -20.f : fa.w));
            float v4 = ex2(cT * ((fb.x < 0.f) ? -20.f : fb.x));
            float v5 = ex2(cT * ((fb.y < 0.f) ? -20.f : fb.y));
            float v6 = ex2(cT * ((fb.z < 0.f) ? -20.f : fb.z));
            float v7 = ex2(cT * ((fb.w < 0.f) ? -20.f : fb.w));
            float sm = ((v0 + v1) + (v2 + v3)) + ((v4 + v5) + (v6 + v7));
            sm += __shfl_xor_sync(FULL, sm, 1);
            sm += __shfl_xor_sync(FULL, sm, 2);
            sm += __shfl_xor_sync(FULL, sm, 4);
            float rs = frcp(sm);
            uint4 oa, ob;
            oa.x = totf32(v0 * rs); oa.y = totf32(v1 * rs);
            oa.z = totf32(v2 * rs); oa.w = totf32(v3 * rs);
            ob.x = totf32(v4 * rs); ob.y = totf32(v5 * rs);
            ob.z = totf32(v6 * rs); ob.w = totf32(v7 * rs);
            *(uint4*)rowp = oa;
            *(uint4*)(rowp + 4) = ob;
        }
        __syncthreads();

        {
            const u32* kB = (const u32*)kbuf;
            u32 bf[2][3][2];
            #pragma unroll
            for (int kt = 0; kt < 2; kt++)
                #pragma unroll
                for (int nt = 0; nt < 3; nt++)
                    if (nt < nts){
                        float b0 = vbuf[(kt * 8 + tig) * 72 + e0 + nt * 8 + g];
                        float b1 = vbuf[(kt * 8 + tig + 4) * 72 + e0 + nt * 8 + g];
                        bf[kt][nt][0] = totf32(b0);
                        bf[kt][nt][1] = totf32(b1);
                    }
            #pragma unroll
            for (int mt = 0; mt < 4; mt++){
                #pragma unroll
                for (int kt = 0; kt < 2; kt++){
                    u32 a0 = kB[(kt * 8 + tig) * 72 + mt * 16 + g];
                    u32 a1 = kB[(kt * 8 + tig) * 72 + mt * 16 + g + 8];
                    u32 a2 = kB[(kt * 8 + tig + 4) * 72 + mt * 16 + g];
                    u32 a3 = kB[(kt * 8 + tig + 4) * 72 + mt * 16 + g + 8];
                    #pragma unroll
                    for (int nt = 0; nt < 3; nt++)
                        if (nt < nts) MMA_TF32(C[mt][nt], a0, a1, a2, a3,
                                               bf[kt][nt][0], bf[kt][nt][1]);
                }
            }
        }
        __syncthreads();
        buf ^= 1;
    }

    float* Mp = g_Mp + (long)bx * 4096;
    #pragma unroll
    for (int mt = 0; mt < 4; mt++){
        #pragma unroll
        for (int nt = 0; nt < 3; nt++){
            if (nt >= nts) continue;
            if (w == 3 && nt == 2){
                if (tig == 0){
                    g_Sp[bx * 64 + mt * 16 + g]     = C[mt][2][0];
                    g_Sp[bx * 64 + mt * 16 + g + 8] = C[mt][2][2];
                }
            } else {
                const int e = e0 + nt * 8 + 2 * tig;
                *(float2*)(Mp + (mt * 16 + g) * 64 + e)
                    = make_float2(C[mt][nt][0], C[mt][nt][1]);
                *(float2*)(Mp + (mt * 16 + g + 8) * 64 + e)
                    = make_float2(C[mt][nt][2], C[mt][nt][3]);
            }
        }
    }
}

// =====================================================================
// out_mma: out[l] = g_l * (E_l @ M) via tf32 MMA. grid 512 (4 CTAs/bh),
// block 128. CTA owns 1024 L-rows = 64 double-buffered 16-row tiles.
// Warp w owns output cols [16w, 16w+16) as 2 n-tiles; M B-fragments
// register-resident (32 regs). Phase B: 8 thr/row exp + sums + g.
// =====================================================================
__global__ __launch_bounds__(128, 4) void out_mma(
    const float* __restrict__ Qp, float* __restrict__ Out,
    const float* __restrict__ delta)
{
    __shared__ float pool[4608];   // init: sM[64][68]; then q tiles 2x1152
    __shared__ float sSh[64];
    __shared__ float sg[16];

    const int bx   = blockIdx.x;
    const int bh   = bx >> 2;
    const int b    = bh >> 4, h = bh & 15;
    const int tid  = threadIdx.x;
    const int w    = tid >> 5, lane = tid & 31;
    const int g    = lane >> 2, tig = lane & 3;
    const int e0   = w * 16;

    const float cT = get_cT(delta);
    const long cbase = ((long)b * 4096L) * 1024L + h * 64L;
    const long Lbase = (long)(bx & 3) * 1024;
    const u32 sb = (u32)__cvta_generic_to_shared(pool);

    if (tid < 64){
        float s = 0.f;
        #pragma unroll
        for (int p = 0; p < 4; p++) s += g_Sp[(bh * 4 + p) * 64 + tid];
        sSh[tid] = s;
    }
    // sum 4 M partials into pool as sM[d*68 + e]
    for (int i = tid; i < 1024; i += 128){
        const int d = i >> 4, c4 = (i & 15) * 4;
        float4 a = make_float4(0.f, 0.f, 0.f, 0.f);
        #pragma unroll
        for (int p = 0; p < 4; p++){
            float4 v = *(const float4*)(g_Mp + (long)(bh * 4 + p) * 4096 + d * 64 + c4);
            a.x += v.x; a.y += v.y; a.z += v.z; a.w += v.w;
        }
        *(float4*)(pool + d * 68 + c4) = a;
    }
    __syncthreads();

    // B fragments: BF[nt][kt] = M[k=d][n=e] slice for this warp
    u32 BF[2][8][2];
    #pragma unroll
    for (int nt = 0; nt < 2; nt++)
        #pragma unroll
        for (int kt = 0; kt < 8; kt++){
            BF[nt][kt][0] = totf32(pool[(kt * 8 + tig)     * 68 + e0 + nt * 8 + g]);
            BF[nt][kt][1] = totf32(pool[(kt * 8 + tig + 4) * 68 + e0 + nt * 8 + g]);
        }
    __syncthreads();   // pool recycles as q tile buffers

    auto load_tile = [&](int t, int buf){
        const long l0 = Lbase + (long)t * 16;
        const u32 dbase = sb + (u32)(buf * 1152) * 4;
        #pragma unroll
        for (int i = 0; i < 2; i++){
            int slot = tid + 128 * i;          // 0..255
            int r = slot >> 4, ch = slot & 15;
            cpa16(dbase + (u32)(r * 72 + ch * 4) * 4, Qp + cbase + (l0 + r) * 1024 + ch * 4);
        }
        cp_commit();
    };

    load_tile(0, 0);

    int buf = 0;
    for (int t = 0; t < 64; t++){
        if (t + 1 < 64){ load_tile(t + 1, buf ^ 1); cp_wait1(); }
        else cp_wait0();
        __syncthreads();

        float* qb = pool + buf * 1152;

        // ---- Phase B: exp, row sums (sm, u), g; store tf32 in place ----
        {
            const int row = tid >> 3, sub = tid & 7;
            float* rowp = qb + row * 72 + sub * 8;
            const float* sp = sSh + sub * 8;
            float4 fa = *(float4*)rowp;
            float4 fb = *(float4*)(rowp + 4);
            float4 sa = *(const float4*)sp;
            float4 sbv = *(const float4*)(sp + 4);
            float v0 = ex2(cT * ((fa.x < 0.f) ? -20.f : fa.x));
            float v1 = ex2(cT * ((fa.y < 0.f) ? -20.f : fa.y));
            float v2 = ex2(cT * ((fa.z < 0.f) ? -20.f : fa.z));
            float v3 = ex2(cT * ((fa.w < 0.f) ? -20.f : fa.w));
            float v4 = ex2(cT * ((fb.x < 0.f) ? -20.f : fb.x));
            float v5 = ex2(cT * ((fb.y < 0.f) ? -20.f : fb.y));
            float v6 = ex2(cT * ((fb.z < 0.f) ? -20.f : fb.z));
            float v7 = ex2(cT * ((fb.w < 0.f) ? -20.f : fb.w));
            float sm = ((v0 + v1) + (v2 + v3)) + ((v4 + v5) + (v6 + v7));
            float u  = fmaf(v0, sa.x, fmaf(v1, sa.y, fmaf(v2, sa.z, fmaf(v3, sa.w,
                       fmaf(v4, sbv.x, fmaf(v5, sbv.y, fmaf(v6, sbv.z, v7 * sbv.w)))))));
            #pragma unroll
            for (int o = 1; o <= 4; o <<= 1){
                sm += __shfl_xor_sync(FULL, sm, o);
                u  += __shfl_xor_sync(FULL, u,  o);
            }
            if (sub == 0) sg[row] = frcp(u + 1e-6f * sm);
            uint4 oa, ob;
            oa.x = totf32(v0); oa.y = totf32(v1); oa.z = totf32(v2); oa.w = totf32(v3);
            ob.x = totf32(v4); ob.y = totf32(v5); ob.z = totf32(v6); ob.w = totf32(v7);
            *(uint4*)rowp = oa;
            *(uint4*)(rowp + 4) = ob;
        }
        __syncthreads();

        // ---- Phase C: 8 k-steps x 2 n-tiles MMA + scaled store ----
        {
            const u32* qB = (const u32*)qb;
            float C0[4] = {0.f, 0.f, 0.f, 0.f};
            float C1[4] = {0.f, 0.f, 0.f, 0.f};
            #pragma unroll
            for (int kt = 0; kt < 8; kt++){
                u32 a0 = qB[g * 72       + kt * 8 + tig];
                u32 a1 = qB[(g + 8) * 72 + kt * 8 + tig];
                u32 a2 = qB[g * 72       + kt * 8 + tig + 4];
                u32 a3 = qB[(g + 8) * 72 + kt * 8 + tig + 4];
                MMA_TF32(C0, a0, a1, a2, a3, BF[0][kt][0], BF[0][kt][1]);
                MMA_TF32(C1, a0, a1, a2, a3, BF[1][kt][0], BF[1][kt][1]);
            }
            const float gv0 = sg[g], gv1 = sg[g + 8];
            const long l0 = Lbase + (long)t * 16;
            float* o0 = Out + cbase + (l0 + g) * 1024 + e0 + 2 * tig;
            float* o1 = Out + cbase + (l0 + g + 8) * 1024 + e0 + 2 * tig;
            *(float2*)o0       = make_float2(C0[0] * gv0, C0[1] * gv0);
            *(float2*)(o0 + 8) = make_float2(C1[0] * gv0, C1[1] * gv0);
            *(float2*)o1       = make_float2(C0[2] * gv1, C0[3] * gv1);
            *(float2*)(o1 + 8) = make_float2(C1[2] * gv1, C1[3] * gv1);
        }
        __syncthreads();
        buf ^= 1;
    }
}

extern "C" void kernel_launch(void* const* d_in, const int* in_sizes, int n_in,
                              void* d_out, int out_size)
{
    const float* Q     = (const float*)d_in[0];
    const float* K     = (const float*)d_in[1];
    const float* V     = (const float*)d_in[2];
    const float* delta = (const float*)d_in[3];
    float* Out = (float*)d_out;

    kv_mma<<<512, 128>>>(K, V, delta);
    out_mma<<<512, 128>>>(Q, Out, delta);
}

// round 11
// speedup vs baseline: 2.0651x; 1.0657x over previous
#include <cuda_runtime.h>
#include <cstdint>

typedef unsigned long long u64;
typedef unsigned int u32;
#define FULL 0xFFFFFFFFu

__device__ __forceinline__ float ex2(float x){
    float r; asm("ex2.approx.f32 %0,%1;" : "=f"(r) : "f"(x)); return r;
}
__device__ __forceinline__ float frcp(float x){
    float r; asm("rcp.approx.f32 %0,%1;" : "=f"(r) : "f"(x)); return r;
}
__device__ __forceinline__ u32 totf32(float x){
    u32 r; asm("cvt.rna.tf32.f32 %0,%1;" : "=r"(r) : "f"(x)); return r;
}
__device__ __forceinline__ void cpa16(u32 dst, const void* src){
    asm volatile("cp.async.cg.shared.global [%0], [%1], 16;" :: "r"(dst), "l"(src));
}
__device__ __forceinline__ void cp_commit(){ asm volatile("cp.async.commit_group;"); }
__device__ __forceinline__ void cp_wait1(){ asm volatile("cp.async.wait_group 1;"); }
__device__ __forceinline__ void cp_wait0(){ asm volatile("cp.async.wait_group 0;"); }

// per-CTA partials: [bh*4 + q4]
__device__ float g_Mp[512 * 4096];
__device__ float g_Sp[512 * 64];

__device__ __forceinline__ float get_cT(const float* __restrict__ delta){
    float d = delta[0];
    float t = (d > 20.f) ? d : log1pf(expf(d));
    return 1.44269504088896f / t;
}

#define MMA_TF32(C, a0,a1,a2,a3, b0,b1) \
    asm("mma.sync.aligned.m16n8k8.row.col.f32.tf32.tf32.f32 " \
        "{%0,%1,%2,%3},{%4,%5,%6,%7},{%8,%9},{%0,%1,%2,%3};" \
        : "+f"((C)[0]),"+f"((C)[1]),"+f"((C)[2]),"+f"((C)[3]) \
        : "r"(a0),"r"(a1),"r"(a2),"r"(a3), "r"(b0),"r"(b1))

// =====================================================================
// kv_mma: unchanged from round 9/10 (measured ~72us).
// =====================================================================
__global__ __launch_bounds__(128, 4) void kv_mma(
    const float* __restrict__ Kp, const float* __restrict__ Vp,
    const float* __restrict__ delta)
{
    __shared__ float pool[4608];

    const int bx   = blockIdx.x;
    const int bh   = bx >> 2;
    const int b    = bh >> 4, h = bh & 15;
    const int tid  = threadIdx.x;
    const int w    = tid >> 5, lane = tid & 31;
    const int g    = lane >> 2, tig = lane & 3;

    const float cT = get_cT(delta);
    const long cbase = ((long)b * 4096L) * 1024L + h * 64L;
    const float* kglob = Kp + cbase;
    const float* vglob = Vp + cbase;
    const long Lbase = (long)(bx & 3) * 1024;

    const u32 sb = (u32)__cvta_generic_to_shared(pool);

    for (int idx = tid; idx < 256; idx += 128){
        int buf = idx >> 7, rem = idx & 127;
        int row = rem >> 3, col = 64 + (rem & 7);
        pool[2304 + buf * 1152 + row * 72 + col] = (col == 64) ? 1.f : 0.f;
    }
    __syncthreads();

    float C[4][3][4];
    #pragma unroll
    for (int mt = 0; mt < 4; mt++)
        #pragma unroll
        for (int nt = 0; nt < 3; nt++)
            #pragma unroll
            for (int i = 0; i < 4; i++) C[mt][nt][i] = 0.f;
    const int nts = (w == 3) ? 3 : 2;
    const int e0  = w * 16;

    auto load_tile = [&](int t, int buf){
        const long l0 = Lbase + (long)t * 16;
        const float* src = (w < 2) ? kglob : vglob;
        const u32 dbase = sb + ((w < 2 ? 0 : 2304) + buf * 1152) * 4;
        #pragma unroll
        for (int i = 0; i < 4; i++){
            int slot = lane + 32 * i;
            int r = (w & 1) * 8 + (slot >> 4);
            int ch = slot & 15;
            cpa16(dbase + (u32)(r * 72 + ch * 4) * 4, src + (l0 + r) * 1024 + ch * 4);
        }
        cp_commit();
    };

    load_tile(0, 0);

    int buf = 0;
    for (int t = 0; t < 64; t++){
        if (t + 1 < 64){ load_tile(t + 1, buf ^ 1); cp_wait1(); }
        else cp_wait0();
        __syncthreads();

        float* kbuf = pool + buf * 1152;
        const float* vbuf = pool + 2304 + buf * 1152;

        {
            const int row = tid >> 3, sub = tid & 7;
            float* rowp = kbuf + row * 72 + sub * 8;
            float4 fa = *(float4*)rowp;
            float4 fb = *(float4*)(rowp + 4);
            float v0 = ex2(cT * ((fa.x < 0.f) ? -20.f : fa.x));
            float v1 = ex2(cT * ((fa.y < 0.f) ? -20.f : fa.y));
            float v2 = ex2(cT * ((fa.z < 0.f) ? -20.f : fa.z));
            float v3 = ex2(cT * ((fa.w < 0.f) ? -20.f : fa.w));
            float v4 = ex2(cT * ((fb.x < 0.f) ? -20.f : fb.x));
            float v5 = ex2(cT * ((fb.y < 0.f) ? -20.f : fb.y));
            float v6 = ex2(cT * ((fb.z < 0.f) ? -20.f : fb.z));
            float v7 = ex2(cT * ((fb.w < 0.f) ? -20.f : fb.w));
            float sm = ((v0 + v1) + (v2 + v3)) + ((v4 + v5) + (v6 + v7));
            sm += __shfl_xor_sync(FULL, sm, 1);
            sm += __shfl_xor_sync(FULL, sm, 2);
            sm += __shfl_xor_sync(FULL, sm, 4);
            float rs = frcp(sm);
            uint4 oa, ob;
            oa.x = totf32(v0 * rs); oa.y = totf32(v1 * rs);
            oa.z = totf32(v2 * rs); oa.w = totf32(v3 * rs);
            ob.x = totf32(v4 * rs); ob.y = totf32(v5 * rs);
            ob.z = totf32(v6 * rs); ob.w = totf32(v7 * rs);
            *(uint4*)rowp = oa;
            *(uint4*)(rowp + 4) = ob;
        }
        __syncthreads();

        {
            const u32* kB = (const u32*)kbuf;
            u32 bf[2][3][2];
            #pragma unroll
            for (int kt = 0; kt < 2; kt++)
                #pragma unroll
                for (int nt = 0; nt < 3; nt++)
                    if (nt < nts){
                        float b0 = vbuf[(kt * 8 + tig) * 72 + e0 + nt * 8 + g];
                        float b1 = vbuf[(kt * 8 + tig + 4) * 72 + e0 + nt * 8 + g];
                        bf[kt][nt][0] = totf32(b0);
                        bf[kt][nt][1] = totf32(b1);
                    }
            #pragma unroll
            for (int mt = 0; mt < 4; mt++){
                #pragma unroll
                for (int kt = 0; kt < 2; kt++){
                    u32 a0 = kB[(kt * 8 + tig) * 72 + mt * 16 + g];
                    u32 a1 = kB[(kt * 8 + tig) * 72 + mt * 16 + g + 8];
                    u32 a2 = kB[(kt * 8 + tig + 4) * 72 + mt * 16 + g];
                    u32 a3 = kB[(kt * 8 + tig + 4) * 72 + mt * 16 + g + 8];
                    #pragma unroll
                    for (int nt = 0; nt < 3; nt++)
                        if (nt < nts) MMA_TF32(C[mt][nt], a0, a1, a2, a3,
                                               bf[kt][nt][0], bf[kt][nt][1]);
                }
            }
        }
        __syncthreads();
        buf ^= 1;
    }

    float* Mp = g_Mp + (long)bx * 4096;
    #pragma unroll
    for (int mt = 0; mt < 4; mt++){
        #pragma unroll
        for (int nt = 0; nt < 3; nt++){
            if (nt >= nts) continue;
            if (w == 3 && nt == 2){
                if (tig == 0){
                    g_Sp[bx * 64 + mt * 16 + g]     = C[mt][2][0];
                    g_Sp[bx * 64 + mt * 16 + g + 8] = C[mt][2][2];
                }
            } else {
                const int e = e0 + nt * 8 + 2 * tig;
                *(float2*)(Mp + (mt * 16 + g) * 64 + e)
                    = make_float2(C[mt][nt][0], C[mt][nt][1]);
                *(float2*)(Mp + (mt * 16 + g + 8) * 64 + e)
                    = make_float2(C[mt][nt][2], C[mt][nt][3]);
            }
        }
    }
}

// =====================================================================
// out_mma v2: warps split l (not e). grid 1024 (8 CTAs/bh, 512 rows
// each), block 128, 2 CTAs/SM. Tile = 64 rows (stride 68, conflict-
// free A loads), double-buffered. Warp w owns rows [16w,16w+16) x all
// 64 e; M B-fragments fully register-resident (128 regs, loaded once).
// Per tile per warp: 32 unique LDS.32 A-frag loads + 64 MMAs.
// =====================================================================
__global__ __launch_bounds__(128, 2) void out_mma(
    const float* __restrict__ Qp, float* __restrict__ Out,
    const float* __restrict__ delta)
{
    __shared__ float pool[8704];   // init: sM[64][68]; then 2 tile buffers [64][68]
    __shared__ float sSh[64];
    __shared__ float sg[64];

    const int bx   = blockIdx.x;
    const int bh   = bx >> 3;
    const int b    = bh >> 4, h = bh & 15;
    const int tid  = threadIdx.x;
    const int w    = tid >> 5, lane = tid & 31;
    const int g    = lane >> 2, tig = lane & 3;

    const float cT = get_cT(delta);
    const long cbase = ((long)b * 4096L) * 1024L + h * 64L;
    const long Lbase = (long)(bx & 7) * 512;
    const u32 sb = (u32)__cvta_generic_to_shared(pool);

    if (tid < 64){
        float s = 0.f;
        #pragma unroll
        for (int p = 0; p < 4; p++) s += g_Sp[(bh * 4 + p) * 64 + tid];
        sSh[tid] = s;
    }
    // sum 4 M partials into pool as sM[d*68 + e]
    for (int i = tid; i < 1024; i += 128){
        const int d = i >> 4, c4 = (i & 15) * 4;
        float4 a = make_float4(0.f, 0.f, 0.f, 0.f);
        #pragma unroll
        for (int p = 0; p < 4; p++){
            float4 v = *(const float4*)(g_Mp + (long)(bh * 4 + p) * 4096 + d * 64 + c4);
            a.x += v.x; a.y += v.y; a.z += v.z; a.w += v.w;
        }
        *(float4*)(pool + d * 68 + c4) = a;
    }
    __syncthreads();

    // register-resident M B-fragments: BF[kt][nt][2]
    u32 BF[8][8][2];
    #pragma unroll
    for (int kt = 0; kt < 8; kt++)
        #pragma unroll
        for (int nt = 0; nt < 8; nt++){
            BF[kt][nt][0] = totf32(pool[(kt * 8 + tig)     * 68 + nt * 8 + g]);
            BF[kt][nt][1] = totf32(pool[(kt * 8 + tig + 4) * 68 + nt * 8 + g]);
        }
    __syncthreads();   // pool recycles as q tile buffers

    auto load_tile = [&](int t, int buf){
        const long l0 = Lbase + (long)t * 64;
        const u32 dbase = sb + (u32)(buf * 4352) * 4;
        #pragma unroll
        for (int i = 0; i < 8; i++){
            int slot = tid + 128 * i;          // 0..1023
            int r = slot >> 4, ch = slot & 15;
            cpa16(dbase + (u32)(r * 68 + ch * 4) * 4, Qp + cbase + (l0 + r) * 1024 + ch * 4);
        }
        cp_commit();
    };

    load_tile(0, 0);

    int buf = 0;
    for (int t = 0; t < 8; t++){
        if (t + 1 < 8){ load_tile(t + 1, buf ^ 1); cp_wait1(); }
        else cp_wait0();
        __syncthreads();

        float* qb = pool + buf * 4352;

        // ---- Phase B: exp, row sums, g; store tf32 in place. 4 passes ----
        #pragma unroll
        for (int p = 0; p < 4; p++){
            const int row = p * 16 + (tid >> 3), sub = tid & 7;
            float* rowp = qb + row * 68 + sub * 8;
            const float* sp = sSh + sub * 8;
            float4 fa = *(float4*)rowp;
            float4 fb = *(float4*)(rowp + 4);
            float4 sa = *(const float4*)sp;
            float4 sbv = *(const float4*)(sp + 4);
            float v0 = ex2(cT * ((fa.x < 0.f) ? -20.f : fa.x));
            float v1 = ex2(cT * ((fa.y < 0.f) ? -20.f : fa.y));
            float v2 = ex2(cT * ((fa.z < 0.f) ? -20.f : fa.z));
            float v3 = ex2(cT * ((fa.w < 0.f) ? -20.f : fa.w));
            float v4 = ex2(cT * ((fb.x < 0.f) ? -20.f : fb.x));
            float v5 = ex2(cT * ((fb.y < 0.f) ? -20.f : fb.y));
            float v6 = ex2(cT * ((fb.z < 0.f) ? -20.f : fb.z));
            float v7 = ex2(cT * ((fb.w < 0.f) ? -20.f : fb.w));
            float sm = ((v0 + v1) + (v2 + v3)) + ((v4 + v5) + (v6 + v7));
            float u  = fmaf(v0, sa.x, fmaf(v1, sa.y, fmaf(v2, sa.z, fmaf(v3, sa.w,
                       fmaf(v4, sbv.x, fmaf(v5, sbv.y, fmaf(v6, sbv.z, v7 * sbv.w)))))));
            #pragma unroll
            for (int o = 1; o <= 4; o <<= 1){
                sm += __shfl_xor_sync(FULL, sm, o);
                u  += __shfl_xor_sync(FULL, u,  o);
            }
            if (sub == 0) sg[row] = frcp(u + 1e-6f * sm);
            uint4 oa, ob;
            oa.x = totf32(v0); oa.y = totf32(v1); oa.z = totf32(v2); oa.w = totf32(v3);
            ob.x = totf32(v4); ob.y = totf32(v5); ob.z = totf32(v6); ob.w = totf32(v7);
            *(uint4*)rowp = oa;
            *(uint4*)(rowp + 4) = ob;
        }
        __syncthreads();

        // ---- Phase C: warp w owns rows [16w,16w+16); 8 kt x 8 nt MMAs ----
        {
            const u32* qB = (const u32*)(qb + 16 * w * 68);
            float C[8][4];
            #pragma unroll
            for (int nt = 0; nt < 8; nt++)
                #pragma unroll
                for (int i = 0; i < 4; i++) C[nt][i] = 0.f;
            #pragma unroll
            for (int kt = 0; kt < 8; kt++){
                u32 a0 = qB[g * 68       + kt * 8 + tig];
                u32 a1 = qB[(g + 8) * 68 + kt * 8 + tig];
                u32 a2 = qB[g * 68       + kt * 8 + tig + 4];
                u32 a3 = qB[(g + 8) * 68 + kt * 8 + tig + 4];
                #pragma unroll
                for (int nt = 0; nt < 8; nt++)
                    MMA_TF32(C[nt], a0, a1, a2, a3, BF[kt][nt][0], BF[kt][nt][1]);
            }
            const float gv0 = sg[16 * w + g], gv1 = sg[16 * w + g + 8];
            const long l0 = Lbase + (long)t * 64 + 16 * w;
            float* o0 = Out + cbase + (l0 + g) * 1024 + 2 * tig;
            float* o1 = Out + cbase + (l0 + g + 8) * 1024 + 2 * tig;
            #pragma unroll
            for (int nt = 0; nt < 8; nt++){
                *(float2*)(o0 + nt * 8) = make_float2(C[nt][0] * gv0, C[nt][1] * gv0);
                *(float2*)(o1 + nt * 8) = make_float2(C[nt][2] * gv1, C[nt][3] * gv1);
            }
        }
        __syncthreads();
        buf ^= 1;
    }
}

extern "C" void kernel_launch(void* const* d_in, const int* in_sizes, int n_in,
                              void* d_out, int out_size)
{
    const float* Q     = (const float*)d_in[0];
    const float* K     = (const float*)d_in[1];
    const float* V     = (const float*)d_in[2];
    const float* delta = (const float*)d_in[3];
    float* Out = (float*)d_out;

    kv_mma<<<512, 128>>>(K, V, delta);
    out_mma<<<1024, 128>>>(Q, Out, delta);
}

// round 12
// speedup vs baseline: 2.3291x; 1.1278x over previous
#include <cuda_runtime.h>
#include <cstdint>

typedef unsigned long long u64;
typedef unsigned int u32;
#define FULL 0xFFFFFFFFu

__device__ __forceinline__ float ex2(float x){
    float r; asm("ex2.approx.f32 %0,%1;" : "=f"(r) : "f"(x)); return r;
}
__device__ __forceinline__ float frcp(float x){
    float r; asm("rcp.approx.f32 %0,%1;" : "=f"(r) : "f"(x)); return r;
}
__device__ __forceinline__ u32 totf32(float x){
    u32 r; asm("cvt.rna.tf32.f32 %0,%1;" : "=r"(r) : "f"(x)); return r;
}
__device__ __forceinline__ void cpa16(u32 dst, const void* src){
    asm volatile("cp.async.cg.shared.global [%0], [%1], 16;" :: "r"(dst), "l"(src));
}
__device__ __forceinline__ void cp_commit(){ asm volatile("cp.async.commit_group;"); }
__device__ __forceinline__ void cp_wait1(){ asm volatile("cp.async.wait_group 1;"); }
__device__ __forceinline__ void cp_wait0(){ asm volatile("cp.async.wait_group 0;"); }

// per-CTA partials: [bh*4 + q4]
__device__ float g_Mp[512 * 4096];
__device__ float g_Sp[512 * 64];

__device__ __forceinline__ float get_cT(const float* __restrict__ delta){
    float d = delta[0];
    float t = (d > 20.f) ? d : log1pf(expf(d));
    return 1.44269504088896f / t;
}

#define MMA_TF32(C, a0,a1,a2,a3, b0,b1) \
    asm("mma.sync.aligned.m16n8k8.row.col.f32.tf32.tf32.f32 " \
        "{%0,%1,%2,%3},{%4,%5,%6,%7},{%8,%9},{%0,%1,%2,%3};" \
        : "+f"((C)[0]),"+f"((C)[1]),"+f"((C)[2]),"+f"((C)[3]) \
        : "r"(a0),"r"(a1),"r"(a2),"r"(a3), "r"(b0),"r"(b1))

// =====================================================================
// kv_mma: tf32 MMA KV partials. Triple-buffered tiles -> 2 barriers/tile.
// =====================================================================
__global__ __launch_bounds__(128, 4) void kv_mma(
    const float* __restrict__ Kp, const float* __restrict__ Vp,
    const float* __restrict__ delta)
{
    __shared__ float pool[6912];   // k: 3x1152 at 0, v: 3x1152 at 3456

    const int bx   = blockIdx.x;
    const int bh   = bx >> 2;
    const int b    = bh >> 4, h = bh & 15;
    const int tid  = threadIdx.x;
    const int w    = tid >> 5, lane = tid & 31;
    const int g    = lane >> 2, tig = lane & 3;

    const float cT = get_cT(delta);
    const long cbase = ((long)b * 4096L) * 1024L + h * 64L;
    const float* kglob = Kp + cbase;
    const float* vglob = Vp + cbase;
    const long Lbase = (long)(bx & 3) * 1024;

    const u32 sb = (u32)__cvta_generic_to_shared(pool);

    // ones column at e=64 in all three v buffers
    for (int idx = tid; idx < 384; idx += 128){
        int bf3 = idx >> 7, rem = idx & 127;
        int row = rem >> 3, col = 64 + (rem & 7);
        pool[3456 + bf3 * 1152 + row * 72 + col] = (col == 64) ? 1.f : 0.f;
    }
    __syncthreads();

    float C[4][3][4];
    #pragma unroll
    for (int mt = 0; mt < 4; mt++)
        #pragma unroll
        for (int nt = 0; nt < 3; nt++)
            #pragma unroll
            for (int i = 0; i < 4; i++) C[mt][nt][i] = 0.f;
    const int nts = (w == 3) ? 3 : 2;
    const int e0  = w * 16;

    auto load_tile = [&](int t, int bf3){
        const long l0 = Lbase + (long)t * 16;
        const float* src = (w < 2) ? kglob : vglob;
        const u32 dbase = sb + ((w < 2 ? 0 : 3456) + bf3 * 1152) * 4;
        #pragma unroll
        for (int i = 0; i < 4; i++){
            int slot = lane + 32 * i;
            int r = (w & 1) * 8 + (slot >> 4);
            int ch = slot & 15;
            cpa16(dbase + (u32)(r * 72 + ch * 4) * 4, src + (l0 + r) * 1024 + ch * 4);
        }
        cp_commit();
    };

    load_tile(0, 0);

    for (int t = 0; t < 64; t++){
        if (t + 1 < 64){ load_tile(t + 1, (t + 1) % 3); cp_wait1(); }
        else cp_wait0();
        __syncthreads();

        float* kbuf = pool + (t % 3) * 1152;
        const float* vbuf = pool + 3456 + (t % 3) * 1152;

        {
            const int row = tid >> 3, sub = tid & 7;
            float* rowp = kbuf + row * 72 + sub * 8;
            float4 fa = *(float4*)rowp;
            float4 fb = *(float4*)(rowp + 4);
            float v0 = ex2(cT * ((fa.x < 0.f) ? -20.f : fa.x));
            float v1 = ex2(cT * ((fa.y < 0.f) ? -20.f : fa.y));
            float v2 = ex2(cT * ((fa.z < 0.f) ? -20.f : fa.z));
            float v3 = ex2(cT * ((fa.w < 0.f) ? -20.f : fa.w));
            float v4 = ex2(cT * ((fb.x < 0.f) ? -20.f : fb.x));
            float v5 = ex2(cT * ((fb.y < 0.f) ? -20.f : fb.y));
            float v6 = ex2(cT * ((fb.z < 0.f) ? -20.f : fb.z));
            float v7 = ex2(cT * ((fb.w < 0.f) ? -20.f : fb.w));
            float sm = ((v0 + v1) + (v2 + v3)) + ((v4 + v5) + (v6 + v7));
            sm += __shfl_xor_sync(FULL, sm, 1);
            sm += __shfl_xor_sync(FULL, sm, 2);
            sm += __shfl_xor_sync(FULL, sm, 4);
            float rs = frcp(sm);
            uint4 oa, ob;
            oa.x = totf32(v0 * rs); oa.y = totf32(v1 * rs);
            oa.z = totf32(v2 * rs); oa.w = totf32(v3 * rs);
            ob.x = totf32(v4 * rs); ob.y = totf32(v5 * rs);
            ob.z = totf32(v6 * rs); ob.w = totf32(v7 * rs);
            *(uint4*)rowp = oa;
            *(uint4*)(rowp + 4) = ob;
        }
        __syncthreads();

        {
            const u32* kB = (const u32*)kbuf;
            u32 bf[2][3][2];
            #pragma unroll
            for (int kt = 0; kt < 2; kt++)
                #pragma unroll
                for (int nt = 0; nt < 3; nt++)
                    if (nt < nts){
                        float b0 = vbuf[(kt * 8 + tig) * 72 + e0 + nt * 8 + g];
                        float b1 = vbuf[(kt * 8 + tig + 4) * 72 + e0 + nt * 8 + g];
                        bf[kt][nt][0] = totf32(b0);
                        bf[kt][nt][1] = totf32(b1);
                    }
            #pragma unroll
            for (int mt = 0; mt < 4; mt++){
                #pragma unroll
                for (int kt = 0; kt < 2; kt++){
                    u32 a0 = kB[(kt * 8 + tig) * 72 + mt * 16 + g];
                    u32 a1 = kB[(kt * 8 + tig) * 72 + mt * 16 + g + 8];
                    u32 a2 = kB[(kt * 8 + tig + 4) * 72 + mt * 16 + g];
                    u32 a3 = kB[(kt * 8 + tig + 4) * 72 + mt * 16 + g + 8];
                    #pragma unroll
                    for (int nt = 0; nt < 3; nt++)
                        if (nt < nts) MMA_TF32(C[mt][nt], a0, a1, a2, a3,
                                               bf[kt][nt][0], bf[kt][nt][1]);
                }
            }
        }
        // no end barrier: triple buffering + next top barrier protect reuse
    }

    float* Mp = g_Mp + (long)bx * 4096;
    #pragma unroll
    for (int mt = 0; mt < 4; mt++){
        #pragma unroll
        for (int nt = 0; nt < 3; nt++){
            if (nt >= nts) continue;
            if (w == 3 && nt == 2){
                if (tig == 0){
                    g_Sp[bx * 64 + mt * 16 + g]     = C[mt][2][0];
                    g_Sp[bx * 64 + mt * 16 + g + 8] = C[mt][2][2];
                }
            } else {
                const int e = e0 + nt * 8 + 2 * tig;
                *(float2*)(Mp + (mt * 16 + g) * 64 + e)
                    = make_float2(C[mt][nt][0], C[mt][nt][1]);
                *(float2*)(Mp + (mt * 16 + g + 8) * 64 + e)
                    = make_float2(C[mt][nt][2], C[mt][nt][3]);
            }
        }
    }
}

// =====================================================================
// out_mma v3: fused softmax-into-fragments. grid 1024 (8 CTAs/bh),
// block 128, 2 CTAs/SM. Tile 64 rows (stride 68), double-buffered.
// Warp w owns rows [16w,16w+16); thread (g,tig) exponentiates exactly
// its A-fragment elements (rows 16w+g/+8, cols kt*8+tig/+4), row sums
// reduce over tig bits (2 shfls), per-row scale applied at epilogue.
// No phase-B smem writes, no sg/sSh smem in the loop, 2 barriers/tile.
// =====================================================================
__global__ __launch_bounds__(128, 2) void out_mma(
    const float* __restrict__ Qp, float* __restrict__ Out,
    const float* __restrict__ delta)
{
    __shared__ float pool[8704];   // init: sM[64][68]; then 2 tile buffers [64][68]
    __shared__ float sSh[64];

    const int bx   = blockIdx.x;
    const int bh   = bx >> 3;
    const int b    = bh >> 4, h = bh & 15;
    const int tid  = threadIdx.x;
    const int w    = tid >> 5, lane = tid & 31;
    const int g    = lane >> 2, tig = lane & 3;

    const float cT = get_cT(delta);
    const long cbase = ((long)b * 4096L) * 1024L + h * 64L;
    const long Lbase = (long)(bx & 7) * 512;
    const u32 sb = (u32)__cvta_generic_to_shared(pool);

    if (tid < 64){
        float s = 0.f;
        #pragma unroll
        for (int p = 0; p < 4; p++) s += g_Sp[(bh * 4 + p) * 64 + tid];
        sSh[tid] = s;
    }
    // sum 4 M partials into pool as sM[d*68 + e]
    for (int i = tid; i < 1024; i += 128){
        const int d = i >> 4, c4 = (i & 15) * 4;
        float4 a = make_float4(0.f, 0.f, 0.f, 0.f);
        #pragma unroll
        for (int p = 0; p < 4; p++){
            float4 v = *(const float4*)(g_Mp + (long)(bh * 4 + p) * 4096 + d * 64 + c4);
            a.x += v.x; a.y += v.y; a.z += v.z; a.w += v.w;
        }
        *(float4*)(pool + d * 68 + c4) = a;
    }
    __syncthreads();

    // register-resident M B-fragments + this thread's s slice
    u32 BF[8][8][2];
    #pragma unroll
    for (int kt = 0; kt < 8; kt++)
        #pragma unroll
        for (int nt = 0; nt < 8; nt++){
            BF[kt][nt][0] = totf32(pool[(kt * 8 + tig)     * 68 + nt * 8 + g]);
            BF[kt][nt][1] = totf32(pool[(kt * 8 + tig + 4) * 68 + nt * 8 + g]);
        }
    float s_reg[16];
    #pragma unroll
    for (int j = 0; j < 16; j++) s_reg[j] = sSh[tig + 4 * j];
    __syncthreads();   // pool recycles as q tile buffers

    auto load_tile = [&](int t, int buf){
        const long l0 = Lbase + (long)t * 64;
        const u32 dbase = sb + (u32)(buf * 4352) * 4;
        #pragma unroll
        for (int i = 0; i < 8; i++){
            int slot = tid + 128 * i;          // 0..1023
            int r = slot >> 4, ch = slot & 15;
            cpa16(dbase + (u32)(r * 68 + ch * 4) * 4, Qp + cbase + (l0 + r) * 1024 + ch * 4);
        }
        cp_commit();
    };

    load_tile(0, 0);

    int buf = 0;
    for (int t = 0; t < 8; t++){
        if (t + 1 < 8){ load_tile(t + 1, buf ^ 1); cp_wait1(); }
        else cp_wait0();
        __syncthreads();

        const float* r0p = pool + buf * 4352 + (16 * w + g) * 68;
        const float* r1p = r0p + 8 * 68;

        float C[8][4];
        #pragma unroll
        for (int nt = 0; nt < 8; nt++)
            #pragma unroll
            for (int i = 0; i < 4; i++) C[nt][i] = 0.f;

        float sm0 = 0.f, u0 = 0.f, sm1 = 0.f, u1 = 0.f;

        #pragma unroll
        for (int kt = 0; kt < 8; kt++){
            float x0 = r0p[kt * 8 + tig];
            float x1 = r1p[kt * 8 + tig];
            float x2 = r0p[kt * 8 + tig + 4];
            float x3 = r1p[kt * 8 + tig + 4];
            float e0v = ex2(cT * ((x0 < 0.f) ? -20.f : x0));
            float e1v = ex2(cT * ((x1 < 0.f) ? -20.f : x1));
            float e2v = ex2(cT * ((x2 < 0.f) ? -20.f : x2));
            float e3v = ex2(cT * ((x3 < 0.f) ? -20.f : x3));
            sm0 += e0v + e2v;
            sm1 += e1v + e3v;
            u0 = fmaf(e0v, s_reg[2 * kt], fmaf(e2v, s_reg[2 * kt + 1], u0));
            u1 = fmaf(e1v, s_reg[2 * kt], fmaf(e3v, s_reg[2 * kt + 1], u1));
            u32 a0 = totf32(e0v), a1 = totf32(e1v);
            u32 a2 = totf32(e2v), a3 = totf32(e3v);
            #pragma unroll
            for (int nt = 0; nt < 8; nt++)
                MMA_TF32(C[nt], a0, a1, a2, a3, BF[kt][nt][0], BF[kt][nt][1]);
        }

        // row sums live on the 4 tig lanes of each g: reduce over tig bits
        #pragma unroll
        for (int o = 1; o <= 2; o <<= 1){
            sm0 += __shfl_xor_sync(FULL, sm0, o);
            u0  += __shfl_xor_sync(FULL, u0,  o);
            sm1 += __shfl_xor_sync(FULL, sm1, o);
            u1  += __shfl_xor_sync(FULL, u1,  o);
        }
        const float gv0 = frcp(u0 + 1e-6f * sm0);
        const float gv1 = frcp(u1 + 1e-6f * sm1);

        const long l0 = Lbase + (long)t * 64 + 16 * w;
        float* o0 = Out + cbase + (l0 + g) * 1024 + 2 * tig;
        float* o1 = Out + cbase + (l0 + g + 8) * 1024 + 2 * tig;
        #pragma unroll
        for (int nt = 0; nt < 8; nt++){
            *(float2*)(o0 + nt * 8) = make_float2(C[nt][0] * gv0, C[nt][1] * gv0);
            *(float2*)(o1 + nt * 8) = make_float2(C[nt][2] * gv1, C[nt][3] * gv1);
        }
        __syncthreads();
        buf ^= 1;
    }
}

extern "C" void kernel_launch(void* const* d_in, const int* in_sizes, int n_in,
                              void* d_out, int out_size)
{
    const float* Q     = (const float*)d_in[0];
    const float* K     = (const float*)d_in[1];
    const float* V     = (const float*)d_in[2];
    const float* delta = (const float*)d_in[3];
    float* Out = (float*)d_out;

    kv_mma<<<512, 128>>>(K, V, delta);
    out_mma<<<1024, 128>>>(Q, Out, delta);
}